// round 4
// baseline (speedup 1.0000x reference)
#include <cuda_runtime.h>
#include <cstdint>

#define BB 32
#define NN 1024
#define KK 20
#define BN_ 32768          // BB*NN
#define NSLOT 64

// ---------------- scratch (static __device__, no allocations) ----------------
__device__ float g_cat[BN_ * 512];       // x1|x2|x3|x4 concatenated per point
__device__ float g_y[BN_ * 256];         // y = x @ Wa^T
__device__ float g_base[BN_ * 256];      // base = x @ (Wb-Wa)^T
__device__ float g_hmax[BN_ * 256];
__device__ float g_hmin[BN_ * 256];
__device__ float g_pd[(size_t)BB * NN * NN];   // per-batch gram matrix (134MB)
__device__ float g_norm[BN_];
__device__ int   g_idx[BN_ * KK];
__device__ float g_sumslot[NSLOT * 1024];
__device__ float g_sqslot[NSLOT * 1024];
__device__ float g_scale[1024];
__device__ float g_bias[1024];
__device__ unsigned g_bmaxk[BB * 1024];
__device__ unsigned g_bmink[BB * 1024];

__device__ __forceinline__ unsigned encf(float f) {
    int i = __float_as_int(f);
    return (i >= 0) ? ((unsigned)i | 0x80000000u) : ~((unsigned)i);
}
__device__ __forceinline__ float decf(unsigned u) {
    return __int_as_float((u & 0x80000000u) ? (int)(u ^ 0x80000000u) : (int)(~u));
}

// ---------------- packed f32x2 helpers (Blackwell dual-fp32 pipe) -----------
__device__ __forceinline__ unsigned long long packdup(float a) {
    unsigned long long r;
    unsigned ai = __float_as_uint(a);
    asm("mov.b64 %0, {%1, %2};" : "=l"(r) : "r"(ai), "r"(ai));
    return r;
}
__device__ __forceinline__ void fma2(unsigned long long &d, unsigned long long a,
                                     unsigned long long b) {
    asm("fma.rn.f32x2 %0, %1, %2, %0;" : "+l"(d) : "l"(a), "l"(b));
}
__device__ __forceinline__ void unpack2(unsigned long long v, float &lo, float &hi) {
    unsigned l, h;
    asm("mov.b64 {%0, %1}, %2;" : "=r"(l), "=r"(h) : "l"(v));
    lo = __uint_as_float(l); hi = __uint_as_float(h);
}

// ---------------- init ------------------------------------------------------
__global__ void k_init() {
    int i = blockIdx.x * blockDim.x + threadIdx.x;
    if (i < NSLOT * 1024) { g_sumslot[i] = 0.f; g_sqslot[i] = 0.f; }
    if (i < BB * 1024)    { g_bmaxk[i] = 0u;   g_bmink[i] = 0xFFFFFFFFu; }
}

// ---------------- stage1 y/base (C=3, O=64) ---------------------------------
__global__ void k_ybase1(const float* __restrict__ x, const float* __restrict__ W) {
    int bn = blockIdx.x;
    int o  = threadIdx.x;   // 64
    __shared__ float xs[3];
    if (o < 3) xs[o] = x[bn * 3 + o];
    __syncthreads();
    const float* w = W + o * 6;
    float y  = w[0] * xs[0] + w[1] * xs[1] + w[2] * xs[2];
    float bs = (w[3] - w[0]) * xs[0] + (w[4] - w[1]) * xs[1] + (w[5] - w[2]) * xs[2];
    g_y[bn * 64 + o]    = y;
    g_base[bn * 64 + o] = bs;
}

// ---------------- kNN for C=3 only (low register use) -----------------------
__global__ void k_knn3(const float* __restrict__ x) {
    constexpr int TS = 64;
    __shared__ float sc[TS][3];
    __shared__ float snorm[TS];
    int q = blockIdx.x * blockDim.x + threadIdx.x;  // blockDim=128
    int b = q >> 10;
    const float* xb = x + (size_t)b * NN * 3;
    int n = q & 1023;
    float q0 = xb[n * 3 + 0], q1 = xb[n * 3 + 1], q2 = xb[n * 3 + 2];
    float qq = q0 * q0 + q1 * q1 + q2 * q2;

    float vals[KK]; int ids[KK];
#pragma unroll
    for (int i = 0; i < KK; i++) { vals[i] = -1e30f; ids[i] = 0; }

    for (int t = 0; t < NN / TS; t++) {
        __syncthreads();
        for (int i = threadIdx.x; i < TS * 3; i += blockDim.x) {
            sc[i / 3][i % 3] = xb[(size_t)t * TS * 3 + i];
        }
        __syncthreads();
        if (threadIdx.x < TS) {
            float a = sc[threadIdx.x][0], bq = sc[threadIdx.x][1], c = sc[threadIdx.x][2];
            snorm[threadIdx.x] = a * a + bq * bq + c * c;
        }
        __syncthreads();
        for (int mm = 0; mm < TS; mm++) {
            float acc = q0 * sc[mm][0] + q1 * sc[mm][1] + q2 * sc[mm][2];
            float pd = (2.f * acc - qq) - snorm[mm];
            if (pd > vals[KK - 1]) {
                float cv = pd; int ci = t * TS + mm;
#pragma unroll
                for (int i = 0; i < KK; i++) {
                    bool sw = cv > vals[i];
                    float tv = vals[i]; int ti = ids[i];
                    vals[i] = sw ? cv : tv; ids[i] = sw ? ci : ti;
                    cv = sw ? tv : cv;  ci = sw ? ti : ci;
                }
            }
        }
    }
#pragma unroll
    for (int i = 0; i < KK; i++) g_idx[(size_t)q * KK + i] = ids[i];
}

// ---------------- diag of gram -> candidate norms ---------------------------
__global__ void k_diag() {
    int q = blockIdx.x * blockDim.x + threadIdx.x;
    if (q < BN_) g_norm[q] = g_pd[(size_t)q * NN + (q & 1023)];
}

// ---------------- top-20 select from gram rows ------------------------------
__global__ __launch_bounds__(64) void k_select() {
    __shared__ float sm[64][65];
    __shared__ float snrm[64];
    int t = threadIdx.x;           // 64 threads, 1 query each
    int q0 = blockIdx.x * 64;
    int b  = q0 >> 10;
    float qq = g_norm[q0 + t];

    float vals[KK]; int ids[KK];
#pragma unroll
    for (int i = 0; i < KK; i++) { vals[i] = -1e30f; ids[i] = 0; }

    for (int tile = 0; tile < 16; tile++) {
        int c0 = tile * 64;
        __syncthreads();
#pragma unroll
        for (int it = 0; it < 16; it++) {
            int idx4 = it * 64 + t;
            int r = idx4 >> 4, c4 = (idx4 & 15) * 4;
            float4 v = *reinterpret_cast<const float4*>(&g_pd[(size_t)(q0 + r) * NN + c0 + c4]);
            sm[r][c4] = v.x; sm[r][c4 + 1] = v.y; sm[r][c4 + 2] = v.z; sm[r][c4 + 3] = v.w;
        }
        snrm[t] = g_norm[(b << 10) + c0 + t];
        __syncthreads();
        for (int j = 0; j < 64; j++) {
            float key = (2.f * sm[t][j] - qq) - snrm[j];
            if (key > vals[KK - 1]) {
                float cv = key; int ci = c0 + j;
#pragma unroll
                for (int i = 0; i < KK; i++) {
                    bool sw = cv > vals[i];
                    float tv = vals[i]; int ti = ids[i];
                    vals[i] = sw ? cv : tv; ids[i] = sw ? ci : ti;
                    cv = sw ? tv : cv;  ci = sw ? ti : ci;
                }
            }
        }
    }
#pragma unroll
    for (int i = 0; i < KK; i++) g_idx[(size_t)(q0 + t) * KK + i] = ids[i];
}

// ---------------- gather-reduce over k neighbors ----------------------------
__global__ void k_edge_reduce(int O) {
    int bn = blockIdx.x;
    int o  = threadIdx.x;       // O threads
    int b  = bn >> 10;
    __shared__ int soff[KK];
    if (o < KK) soff[o] = ((b << 10) + g_idx[(size_t)bn * KK + o]) * O;
    __syncthreads();
    float bs = g_base[(size_t)bn * O + o];
    float mx = -1e30f, mn = 1e30f, s = 0.f, s2 = 0.f;
#pragma unroll
    for (int j = 0; j < KK; j++) {
        float v = g_y[soff[j] + o] + bs;
        mx = fmaxf(mx, v); mn = fminf(mn, v);
        s += v; s2 += v * v;
    }
    g_hmax[(size_t)bn * O + o] = mx;
    g_hmin[(size_t)bn * O + o] = mn;
    int slot = bn & (NSLOT - 1);
    atomicAdd(&g_sumslot[slot * 1024 + o], s);
    atomicAdd(&g_sqslot[slot * 1024 + o], s2);
}

// ---------------- BN stats finalize (and rezero slots) ----------------------
__global__ void k_stats(const float* __restrict__ g, const float* __restrict__ bt,
                        int O, float invcnt) {
    int o = blockIdx.x * blockDim.x + threadIdx.x;   // 1024 threads total
    float s = 0.f, s2 = 0.f;
    for (int sl = 0; sl < NSLOT; sl++) {
        s  += g_sumslot[sl * 1024 + o];
        s2 += g_sqslot[sl * 1024 + o];
        g_sumslot[sl * 1024 + o] = 0.f;
        g_sqslot[sl * 1024 + o]  = 0.f;
    }
    if (o < O) {
        float mean = s * invcnt;
        float var  = fmaxf(s2 * invcnt - mean * mean, 0.f);
        float sc   = g[o] * rsqrtf(var + 1e-5f);
        g_scale[o] = sc;
        g_bias[o]  = bt[o] - mean * sc;
    }
}

// ---------------- apply BN + LeakyReLU to max/min, write into cat -----------
__global__ void k_apply(int O, int coff) {
    int i = blockIdx.x * blockDim.x + threadIdx.x;
    if (i >= BN_ * O) return;
    int o  = i & (O - 1);        // O is a power of two
    int bn = i / O;
    float sc = g_scale[o];
    float v  = (sc >= 0.f) ? g_hmax[i] : g_hmin[i];
    float hv = fmaf(sc, v, g_bias[o]);
    g_cat[(size_t)bn * 512 + coff + o] = (hv >= 0.f) ? hv : 0.2f * hv;
}

// ---------------- big tiled SGEMM, f32x2 core: 128 x BNT tile, 256 threads --
// A = g_cat+aoff (lda 512). B = W rows (ldw) or, if GRAM, same-batch A rows.
// SUB: B -= Wsub. STATS: stage-5 epilogue. Else write g_y/g_base/g_pd.
template <int BNT, int TN, bool SUB, bool STATS, bool GRAM>
__global__ __launch_bounds__(256) void k_gemm2(
        int aoff, const float* __restrict__ Wa, const float* __restrict__ Wsub,
        int ldw, int Ktot, int ldc, int outsel) {
    __shared__ float As[16][128];
    __shared__ float Bs[16][BNT];
    const float* A = g_cat + aoff;
    const int lda = 512;
    const int m0 = blockIdx.x * 128;
    const int o0 = blockIdx.y * BNT;
    const int tid = threadIdx.x;
    const int trow = tid >> 4;   // 0..15
    const int tcol = tid & 15;   // 0..15

    unsigned long long acc2[8][TN / 2];
#pragma unroll
    for (int i = 0; i < 8; i++)
#pragma unroll
        for (int j = 0; j < TN / 2; j++) acc2[i][j] = 0ULL;

    const int arow = tid >> 1, akoff = (tid & 1) * 8;
    int brow, bkoff;
    if (BNT == 128) { brow = tid >> 1; bkoff = (tid & 1) * 8; }
    else            { brow = tid >> 2; bkoff = (tid & 3) * 4; }

    const float* bbaseptr;
    int ldb;
    if (GRAM) { bbaseptr = A + (size_t)((m0 & ~1023) + o0) * lda; ldb = lda; }
    else      { bbaseptr = Wa + (size_t)o0 * ldw;                  ldb = ldw; }

    for (int kt = 0; kt < Ktot; kt += 16) {
        const float* ap = A + (size_t)(m0 + arow) * lda + kt + akoff;
        float4 a0 = *reinterpret_cast<const float4*>(ap);
        float4 a1 = *reinterpret_cast<const float4*>(ap + 4);
        const float* bp = bbaseptr + (size_t)brow * ldb + kt + bkoff;
        float4 b0 = *reinterpret_cast<const float4*>(bp);
        float4 b1;
        if constexpr (BNT == 128) b1 = *reinterpret_cast<const float4*>(bp + 4);
        if constexpr (SUB) {
            const float* sp = Wsub + (size_t)(o0 + brow) * ldw + kt + bkoff;
            float4 s0 = *reinterpret_cast<const float4*>(sp);
            b0.x -= s0.x; b0.y -= s0.y; b0.z -= s0.z; b0.w -= s0.w;
            if constexpr (BNT == 128) {
                float4 s1 = *reinterpret_cast<const float4*>(sp + 4);
                b1.x -= s1.x; b1.y -= s1.y; b1.z -= s1.z; b1.w -= s1.w;
            }
        }
        __syncthreads();
        As[akoff + 0][arow] = a0.x; As[akoff + 1][arow] = a0.y;
        As[akoff + 2][arow] = a0.z; As[akoff + 3][arow] = a0.w;
        As[akoff + 4][arow] = a1.x; As[akoff + 5][arow] = a1.y;
        As[akoff + 6][arow] = a1.z; As[akoff + 7][arow] = a1.w;
        Bs[bkoff + 0][brow] = b0.x; Bs[bkoff + 1][brow] = b0.y;
        Bs[bkoff + 2][brow] = b0.z; Bs[bkoff + 3][brow] = b0.w;
        if constexpr (BNT == 128) {
            Bs[bkoff + 4][brow] = b1.x; Bs[bkoff + 5][brow] = b1.y;
            Bs[bkoff + 6][brow] = b1.z; Bs[bkoff + 7][brow] = b1.w;
        }
        __syncthreads();
#pragma unroll
        for (int kk = 0; kk < 16; kk++) {
            float av[8];
            *reinterpret_cast<float4*>(&av[0]) = *reinterpret_cast<const float4*>(&As[kk][trow * 8]);
            *reinterpret_cast<float4*>(&av[4]) = *reinterpret_cast<const float4*>(&As[kk][trow * 8 + 4]);
            unsigned long long bv[TN / 2];
            {
                ulonglong2 p0 = *reinterpret_cast<const ulonglong2*>(&Bs[kk][tcol * TN]);
                bv[0] = p0.x; bv[1] = p0.y;
                if constexpr (TN == 8) {
                    ulonglong2 p1 = *reinterpret_cast<const ulonglong2*>(&Bs[kk][tcol * TN + 4]);
                    bv[2] = p1.x; bv[3] = p1.y;
                }
            }
#pragma unroll
            for (int i = 0; i < 8; i++) {
                unsigned long long a2 = packdup(av[i]);
#pragma unroll
                for (int j = 0; j < TN / 2; j++) fma2(acc2[i][j], a2, bv[j]);
            }
        }
    }

    // unpack packed accumulators
    float acc[8][TN];
#pragma unroll
    for (int i = 0; i < 8; i++)
#pragma unroll
        for (int j = 0; j < TN / 2; j++)
            unpack2(acc2[i][j], acc[i][2 * j], acc[i][2 * j + 1]);

    if constexpr (STATS) {
        // stage-5: per-thread reduce 8 rows, then block reduce in As scratch
        int b = m0 >> 10;
        int slot = blockIdx.x & (NSLOT - 1);
        float mx[8], mn[8], sv[8], s2v[8];
#pragma unroll
        for (int j = 0; j < 8; j++) {
            float v = acc[0][j];
            mx[j] = v; mn[j] = v; sv[j] = v; s2v[j] = v * v;
#pragma unroll
            for (int i = 1; i < 8; i++) {
                float w = acc[i][j];
                mx[j] = fmaxf(mx[j], w); mn[j] = fminf(mn[j], w);
                sv[j] += w; s2v[j] += w * w;
            }
        }
        __syncthreads();
#pragma unroll
        for (int j = 0; j < 8; j++) As[trow][tcol * 8 + j] = mx[j];
        __syncthreads();
        if (tid < 128) {
            float r = As[0][tid];
#pragma unroll
            for (int t = 1; t < 16; t++) r = fmaxf(r, As[t][tid]);
            atomicMax(&g_bmaxk[b * 1024 + o0 + tid], encf(r));
        }
        __syncthreads();
#pragma unroll
        for (int j = 0; j < 8; j++) As[trow][tcol * 8 + j] = mn[j];
        __syncthreads();
        if (tid < 128) {
            float r = As[0][tid];
#pragma unroll
            for (int t = 1; t < 16; t++) r = fminf(r, As[t][tid]);
            atomicMin(&g_bmink[b * 1024 + o0 + tid], encf(r));
        }
        __syncthreads();
#pragma unroll
        for (int j = 0; j < 8; j++) As[trow][tcol * 8 + j] = sv[j];
        __syncthreads();
        if (tid < 128) {
            float r = 0.f;
#pragma unroll
            for (int t = 0; t < 16; t++) r += As[t][tid];
            atomicAdd(&g_sumslot[slot * 1024 + o0 + tid], r);
        }
        __syncthreads();
#pragma unroll
        for (int j = 0; j < 8; j++) As[trow][tcol * 8 + j] = s2v[j];
        __syncthreads();
        if (tid < 128) {
            float r = 0.f;
#pragma unroll
            for (int t = 0; t < 16; t++) r += As[t][tid];
            atomicAdd(&g_sqslot[slot * 1024 + o0 + tid], r);
        }
    } else {
        float* cout = GRAM ? g_pd : (outsel ? g_base : g_y);
#pragma unroll
        for (int i = 0; i < 8; i++) {
            int row = m0 + trow * 8 + i;
            float* cp = cout + (size_t)row * ldc + o0 + tcol * TN;
            float4 v0 = make_float4(acc[i][0], acc[i][1], acc[i][2], acc[i][3]);
            *reinterpret_cast<float4*>(cp) = v0;
            if constexpr (TN == 8) {
                float4 v1 = make_float4(acc[i][4], acc[i][5], acc[i][6], acc[i][7]);
                *reinterpret_cast<float4*>(cp + 4) = v1;
            }
        }
    }
}

// ---------------- stage5 finalize: BN + LReLU on per-(b,o) extremum ---------
__global__ void k_final5(float* __restrict__ out) {
    int i = blockIdx.x * blockDim.x + threadIdx.x;   // 32768
    int o = i & 1023;
    float sc = g_scale[o];
    float v  = decf((sc >= 0.f) ? g_bmaxk[i] : g_bmink[i]);
    float hv = fmaf(sc, v, g_bias[o]);
    out[i] = (hv >= 0.f) ? hv : 0.2f * hv;
}

// ---------------- orchestration ---------------------------------------------
extern "C" void kernel_launch(void* const* d_in, const int* in_sizes, int n_in,
                              void* d_out, int out_size) {
    const float* x = (const float*)d_in[0];
    const float *W1 = (const float*)d_in[1],  *G1 = (const float*)d_in[2],  *B1 = (const float*)d_in[3];
    const float *W2 = (const float*)d_in[4],  *G2 = (const float*)d_in[5],  *B2 = (const float*)d_in[6];
    const float *W3 = (const float*)d_in[7],  *G3 = (const float*)d_in[8],  *B3 = (const float*)d_in[9];
    const float *W4 = (const float*)d_in[10], *G4 = (const float*)d_in[11], *B4 = (const float*)d_in[12];
    const float *W5 = (const float*)d_in[13], *G5 = (const float*)d_in[14], *B5 = (const float*)d_in[15];
    float* out = (float*)d_out;

    const float invE = 1.f / (float)((size_t)BN_ * KK);

    k_init<<<256, 256>>>();

    // ---- Stage 1: C=3, O=64, write cat[0:64) ----
    k_ybase1<<<BN_, 64>>>(x, W1);
    k_knn3<<<BN_ / 128, 128>>>(x);
    k_edge_reduce<<<BN_, 64>>>(64);
    k_stats<<<4, 256>>>(G1, B1, 64, invE);
    k_apply<<<BN_ * 64 / 256, 256>>>(64, 0);

    // ---- Stage 2: in=cat[0:64), C=64, O=64 -> cat[64:128) ----
    k_gemm2<64, 4, false, false, false><<<dim3(256, 1), 256>>>(0, W2,      nullptr, 128, 64, 64, 0);
    k_gemm2<64, 4, true,  false, false><<<dim3(256, 1), 256>>>(0, W2 + 64, W2,      128, 64, 64, 1);
    k_gemm2<128, 8, false, false, true><<<dim3(256, 8), 256>>>(0, nullptr, nullptr, 0, 64, 1024, 0);
    k_diag<<<BN_ / 256, 256>>>();
    k_select<<<BN_ / 64, 64>>>();
    k_edge_reduce<<<BN_, 64>>>(64);
    k_stats<<<4, 256>>>(G2, B2, 64, invE);
    k_apply<<<BN_ * 64 / 256, 256>>>(64, 64);

    // ---- Stage 3: in=cat[64:128), C=64, O=128 -> cat[128:256) ----
    k_gemm2<128, 8, false, false, false><<<dim3(256, 1), 256>>>(64, W3,      nullptr, 128, 64, 128, 0);
    k_gemm2<128, 8, true,  false, false><<<dim3(256, 1), 256>>>(64, W3 + 64, W3,      128, 64, 128, 1);
    k_gemm2<128, 8, false, false, true><<<dim3(256, 8), 256>>>(64, nullptr, nullptr, 0, 64, 1024, 0);
    k_diag<<<BN_ / 256, 256>>>();
    k_select<<<BN_ / 64, 64>>>();
    k_edge_reduce<<<BN_, 128>>>(128);
    k_stats<<<4, 256>>>(G3, B3, 128, invE);
    k_apply<<<BN_ * 128 / 256, 256>>>(128, 128);

    // ---- Stage 4: in=cat[128:256), C=128, O=256 -> cat[256:512) ----
    k_gemm2<128, 8, false, false, false><<<dim3(256, 2), 256>>>(128, W4,       nullptr, 256, 128, 256, 0);
    k_gemm2<128, 8, true,  false, false><<<dim3(256, 2), 256>>>(128, W4 + 128, W4,      256, 128, 256, 1);
    k_gemm2<128, 8, false, false, true><<<dim3(256, 8), 256>>>(128, nullptr, nullptr, 0, 128, 1024, 0);
    k_diag<<<BN_ / 256, 256>>>();
    k_select<<<BN_ / 64, 64>>>();
    k_edge_reduce<<<BN_, 256>>>(256);
    k_stats<<<4, 256>>>(G4, B4, 256, invE);
    k_apply<<<BN_ * 256 / 256, 256>>>(256, 256);

    // ---- Stage 5: FC 512->1024 + BN + LReLU + max over points ----
    k_gemm2<128, 8, false, true, false><<<dim3(256, 8), 256>>>(0, W5, nullptr, 512, 512, 1024, 0);
    k_stats<<<4, 256>>>(G5, B5, 1024, 1.f / (float)BN_);
    k_final5<<<128, 256>>>(out);
}

// round 7
// speedup vs baseline: 1.8626x; 1.8626x over previous
#include <cuda_runtime.h>
#include <cuda_bf16.h>
#include <cstdint>

#define BB 32
#define NN 1024
#define KK 20
#define BN_ 32768          // BB*NN
#define NSLOT 64

// ---------------- scratch (static __device__, no allocations) ----------------
__device__ float g_cat[BN_ * 512];            // x1|x2|x3|x4 concatenated per point
__device__ __nv_bfloat16 g_cath[BN_ * 512];   // bf16 3-way split of cat: hi
__device__ __nv_bfloat16 g_catm[BN_ * 512];   // mid
__device__ __nv_bfloat16 g_catl[BN_ * 512];   // lo
__device__ __nv_bfloat16 g_wh[1024 * 512];    // W5 hi
__device__ __nv_bfloat16 g_wl[1024 * 512];    // W5 lo
__device__ float g_y[BN_ * 256];         // y = x @ Wa^T
__device__ float g_base[BN_ * 256];      // base = x @ (Wb-Wa)^T
__device__ float g_hmax[BN_ * 256];
__device__ float g_hmin[BN_ * 256];
__device__ float g_pd[(size_t)BB * NN * NN];   // gram matrix / stage5 H (134MB)
__device__ float g_norm[BN_];
__device__ int   g_idx[BN_ * KK];
__device__ float g_sumslot[NSLOT * 1024];
__device__ float g_sqslot[NSLOT * 1024];
__device__ float g_scale[1024];
__device__ float g_bias[1024];
__device__ float g_max5[BB * 1024];
__device__ float g_min5[BB * 1024];

// ---------------- init ------------------------------------------------------
__global__ void k_init() {
    int i = blockIdx.x * blockDim.x + threadIdx.x;
    if (i < NSLOT * 1024) { g_sumslot[i] = 0.f; g_sqslot[i] = 0.f; }
}

// ---------------- split W5 into bf16 hi/lo ----------------------------------
__global__ void k_convW5(const float* __restrict__ W5) {
    int i = blockIdx.x * blockDim.x + threadIdx.x;   // 1024*512
    float v = W5[i];
    __nv_bfloat16 h = __float2bfloat16(v);
    g_wh[i] = h;
    g_wl[i] = __float2bfloat16(v - __bfloat162float(h));
}

// ---------------- stage1 y/base (C=3, O=64) ---------------------------------
__global__ void k_ybase1(const float* __restrict__ x, const float* __restrict__ W) {
    int bn = blockIdx.x;
    int o  = threadIdx.x;   // 64
    __shared__ float xs[3];
    if (o < 3) xs[o] = x[bn * 3 + o];
    __syncthreads();
    const float* w = W + o * 6;
    float y  = w[0] * xs[0] + w[1] * xs[1] + w[2] * xs[2];
    float bs = (w[3] - w[0]) * xs[0] + (w[4] - w[1]) * xs[1] + (w[5] - w[2]) * xs[2];
    g_y[bn * 64 + o]    = y;
    g_base[bn * 64 + o] = bs;
}

// ---------------- kNN for C=3 only ------------------------------------------
__global__ void k_knn3(const float* __restrict__ x) {
    constexpr int TS = 64;
    __shared__ float sc[TS][3];
    __shared__ float snorm[TS];
    int q = blockIdx.x * blockDim.x + threadIdx.x;  // blockDim=128
    int b = q >> 10;
    const float* xb = x + (size_t)b * NN * 3;
    int n = q & 1023;
    float q0 = xb[n * 3 + 0], q1 = xb[n * 3 + 1], q2 = xb[n * 3 + 2];
    float qq = q0 * q0 + q1 * q1 + q2 * q2;

    float vals[KK]; int ids[KK];
#pragma unroll
    for (int i = 0; i < KK; i++) { vals[i] = -1e30f; ids[i] = 0; }

    for (int t = 0; t < NN / TS; t++) {
        __syncthreads();
        for (int i = threadIdx.x; i < TS * 3; i += blockDim.x) {
            sc[i / 3][i % 3] = xb[(size_t)t * TS * 3 + i];
        }
        __syncthreads();
        if (threadIdx.x < TS) {
            float a = sc[threadIdx.x][0], bq = sc[threadIdx.x][1], c = sc[threadIdx.x][2];
            snorm[threadIdx.x] = a * a + bq * bq + c * c;
        }
        __syncthreads();
        for (int mm = 0; mm < TS; mm++) {
            float acc = q0 * sc[mm][0] + q1 * sc[mm][1] + q2 * sc[mm][2];
            float pd = (2.f * acc - qq) - snorm[mm];
            if (pd > vals[KK - 1]) {
                float cv = pd; int ci = t * TS + mm;
#pragma unroll
                for (int i = 0; i < KK; i++) {
                    bool sw = cv > vals[i];
                    float tv = vals[i]; int ti = ids[i];
                    vals[i] = sw ? cv : tv; ids[i] = sw ? ci : ti;
                    cv = sw ? tv : cv;  ci = sw ? ti : ci;
                }
            }
        }
    }
#pragma unroll
    for (int i = 0; i < KK; i++) g_idx[(size_t)q * KK + i] = ids[i];
}

// ---------------- diag of gram -> candidate norms ---------------------------
__global__ void k_diag() {
    int q = blockIdx.x * blockDim.x + threadIdx.x;
    if (q < BN_) g_norm[q] = g_pd[(size_t)q * NN + (q & 1023)];
}

// ---------------- top-20 select from gram rows ------------------------------
__global__ __launch_bounds__(64) void k_select() {
    __shared__ float sm[64][65];
    __shared__ float snrm[64];
    int t = threadIdx.x;           // 64 threads, 1 query each
    int q0 = blockIdx.x * 64;
    int b  = q0 >> 10;
    float qq = g_norm[q0 + t];

    float vals[KK]; int ids[KK];
#pragma unroll
    for (int i = 0; i < KK; i++) { vals[i] = -1e30f; ids[i] = 0; }

    for (int tile = 0; tile < 16; tile++) {
        int c0 = tile * 64;
        __syncthreads();
#pragma unroll
        for (int it = 0; it < 16; it++) {
            int idx4 = it * 64 + t;
            int r = idx4 >> 4, c4 = (idx4 & 15) * 4;
            float4 v = *reinterpret_cast<const float4*>(&g_pd[(size_t)(q0 + r) * NN + c0 + c4]);
            sm[r][c4] = v.x; sm[r][c4 + 1] = v.y; sm[r][c4 + 2] = v.z; sm[r][c4 + 3] = v.w;
        }
        snrm[t] = g_norm[(b << 10) + c0 + t];
        __syncthreads();
        for (int j = 0; j < 64; j++) {
            float key = (2.f * sm[t][j] - qq) - snrm[j];
            if (key > vals[KK - 1]) {
                float cv = key; int ci = c0 + j;
#pragma unroll
                for (int i = 0; i < KK; i++) {
                    bool sw = cv > vals[i];
                    float tv = vals[i]; int ti = ids[i];
                    vals[i] = sw ? cv : tv; ids[i] = sw ? ci : ti;
                    cv = sw ? tv : cv;  ci = sw ? ti : ci;
                }
            }
        }
    }
#pragma unroll
    for (int i = 0; i < KK; i++) g_idx[(size_t)(q0 + t) * KK + i] = ids[i];
}

// ---------------- gather-reduce over k neighbors ----------------------------
__global__ void k_edge_reduce(int O) {
    int bn = blockIdx.x;
    int o  = threadIdx.x;       // O threads
    int b  = bn >> 10;
    __shared__ int soff[KK];
    if (o < KK) soff[o] = ((b << 10) + g_idx[(size_t)bn * KK + o]) * O;
    __syncthreads();
    float bs = g_base[(size_t)bn * O + o];
    float mx = -1e30f, mn = 1e30f, s = 0.f, s2 = 0.f;
#pragma unroll
    for (int j = 0; j < KK; j++) {
        float v = g_y[soff[j] + o] + bs;
        mx = fmaxf(mx, v); mn = fminf(mn, v);
        s += v; s2 += v * v;
    }
    g_hmax[(size_t)bn * O + o] = mx;
    g_hmin[(size_t)bn * O + o] = mn;
    int slot = bn & (NSLOT - 1);
    atomicAdd(&g_sumslot[slot * 1024 + o], s);
    atomicAdd(&g_sqslot[slot * 1024 + o], s2);
}

// ---------------- BN stats finalize (and rezero slots) ----------------------
__global__ void k_stats(const float* __restrict__ g, const float* __restrict__ bt,
                        int O, float invcnt) {
    int o = blockIdx.x * blockDim.x + threadIdx.x;   // 1024 threads total
    float s = 0.f, s2 = 0.f;
    for (int sl = 0; sl < NSLOT; sl++) {
        s  += g_sumslot[sl * 1024 + o];
        s2 += g_sqslot[sl * 1024 + o];
        g_sumslot[sl * 1024 + o] = 0.f;
        g_sqslot[sl * 1024 + o]  = 0.f;
    }
    if (o < O) {
        float mean = s * invcnt;
        float var  = fmaxf(s2 * invcnt - mean * mean, 0.f);
        float sc   = g[o] * rsqrtf(var + 1e-5f);
        g_scale[o] = sc;
        g_bias[o]  = bt[o] - mean * sc;
    }
}

// -------- apply BN + LReLU to max/min, write cat + 3-way bf16 split ---------
__global__ void k_apply(int O, int coff) {
    int i = blockIdx.x * blockDim.x + threadIdx.x;
    if (i >= BN_ * O) return;
    int o  = i & (O - 1);        // O is a power of two
    int bn = i / O;
    float sc = g_scale[o];
    float v  = (sc >= 0.f) ? g_hmax[i] : g_hmin[i];
    float hv = fmaf(sc, v, g_bias[o]);
    float r  = (hv >= 0.f) ? hv : 0.2f * hv;
    size_t ci = (size_t)bn * 512 + coff + o;
    g_cat[ci] = r;
    __nv_bfloat16 h = __float2bfloat16(r);
    float rm = r - __bfloat162float(h);
    __nv_bfloat16 m = __float2bfloat16(rm);
    g_cath[ci] = h;
    g_catm[ci] = m;
    g_catl[ci] = __float2bfloat16(rm - __bfloat162float(m));
}

// ================= bf16-split tensor-core GEMM (mma.sync, sm_80 path) =======
// D(128x128) = A(128 x Ktot) * B^T.
// GRAM: 3-way split both sides, 6 products (AhBh,AhBm,AmBh,AhBl,AmBm,AlBh).
// else: 2-way split (cat h/m as hi/lo; W5 h/l), 3 products.
// Output: g_pd[(m0+r)*1024 + o0 + c]
#define LDX4(f, addr) \
    asm volatile("ldmatrix.sync.aligned.m8n8.x4.shared.b16 {%0,%1,%2,%3}, [%4];" \
        : "=r"((f)[0]), "=r"((f)[1]), "=r"((f)[2]), "=r"((f)[3]) : "r"(addr))
#define MMA16816(d, a, b0, b1) \
    asm volatile("mma.sync.aligned.m16n8k16.row.col.f32.bf16.bf16.f32 " \
        "{%0,%1,%2,%3},{%4,%5,%6,%7},{%8,%9},{%0,%1,%2,%3};" \
        : "+f"((d)[0]), "+f"((d)[1]), "+f"((d)[2]), "+f"((d)[3]) \
        : "r"((a)[0]), "r"((a)[1]), "r"((a)[2]), "r"((a)[3]), "r"(b0), "r"(b1))

static constexpr int MT_BYTES = 128 * 48;        // one 128x16 bf16 tile, 48B rows

template <bool GRAM>
__global__ __launch_bounds__(256) void k_mma(int aoff, int nchunk) {
    constexpr int NMA  = GRAM ? 3 : 2;
    constexpr int NMB  = GRAM ? 3 : 2;
    constexpr int NMAT = NMA + NMB;
    constexpr int BUFB = NMAT * MT_BYTES;

    extern __shared__ char smem[];
    uint32_t sb;
    asm("{ .reg .u64 t; cvta.to.shared.u64 t, %1; cvt.u32.u64 %0, t; }" : "=r"(sb) : "l"(smem));

    const int tid  = threadIdx.x;
    const int lane = tid & 31;
    const int wid  = tid >> 5;
    const int wm   = wid & 3;          // 4 warps along M
    const int wn   = wid >> 2;         // 2 warps along N
    const int m0   = blockIdx.x * 128;
    const int o0   = blockIdx.y * 128;

    // ---- per-thread cp.async setup (row = tid>>1, half = tid&1) ----
    const int row  = tid >> 1;
    const int half = tid & 1;
    const __nv_bfloat16* gbase[NMAT];
    {
        size_t aio = (size_t)(m0 + row) * 512 + aoff + half * 8;
        gbase[0] = g_cath + aio;
        gbase[1] = g_catm + aio;
        if constexpr (GRAM) gbase[2] = g_catl + aio;
    }
    if constexpr (GRAM) {
        size_t bio = (size_t)((m0 & ~1023) + o0 + row) * 512 + aoff + half * 8;
        gbase[NMA + 0] = g_cath + bio;
        gbase[NMA + 1] = g_catm + bio;
        gbase[NMA + 2] = g_catl + bio;
    } else {
        size_t bio = (size_t)(o0 + row) * 512 + half * 8;
        gbase[NMA + 0] = g_wh + bio;
        gbase[NMA + 1] = g_wl + bio;
    }
    uint32_t soff[NMAT];
#pragma unroll
    for (int j = 0; j < NMAT; j++) soff[j] = sb + j * MT_BYTES + row * 48 + half * 16;

    auto issue = [&](int c, int buf) {
#pragma unroll
        for (int j = 0; j < NMAT; j++) {
            uint32_t sa = soff[j] + buf * BUFB;
            const __nv_bfloat16* gp = gbase[j] + c * 16;
            asm volatile("cp.async.cg.shared.global [%0], [%1], 16;" :: "r"(sa), "l"(gp));
        }
        asm volatile("cp.async.commit_group;");
    };

    // ---- ldmatrix lane addressing ----
    const int arow = (lane & 7) + ((lane >> 3) & 1) * 8;   // A tiles: m-rows
    const int acb  = (lane >> 4) * 16;                     // +16B for k8-15
    const int brow = (lane & 7) + ((lane >> 4) & 1) * 8;   // B tiles: n-rows
    const int bcb  = ((lane >> 3) & 1) * 16;

    float acc[2][8][4];
#pragma unroll
    for (int i = 0; i < 2; i++)
#pragma unroll
        for (int j = 0; j < 8; j++)
#pragma unroll
            for (int q = 0; q < 4; q++) acc[i][j][q] = 0.f;

    issue(0, 0);

    for (int c = 0; c < nchunk; c++) {
        if (c + 1 < nchunk) {
            issue(c + 1, (c + 1) & 1);
            asm volatile("cp.async.wait_group 1;");
        } else {
            asm volatile("cp.async.wait_group 0;");
        }
        __syncthreads();

        const uint32_t bufb = sb + (c & 1) * BUFB;

        uint32_t am[NMA][2][4];
#pragma unroll
        for (int i = 0; i < 2; i++) {
            uint32_t aoffb = (wm * 32 + i * 16 + arow) * 48 + acb;
#pragma unroll
            for (int ma = 0; ma < NMA; ma++)
                LDX4(am[ma][i], bufb + ma * MT_BYTES + aoffb);
        }
#pragma unroll
        for (int g = 0; g < 4; g++) {
            uint32_t boffb = (wn * 64 + g * 16 + brow) * 48 + bcb;
            uint32_t bm[NMB][4];
#pragma unroll
            for (int mb = 0; mb < NMB; mb++)
                LDX4(bm[mb], bufb + (NMA + mb) * MT_BYTES + boffb);
#pragma unroll
            for (int i = 0; i < 2; i++) {
                if constexpr (GRAM) {
                    // 6 products: (0,0) (0,1) (1,0) (0,2) (1,1) (2,0)
                    MMA16816(acc[i][2 * g],     am[0][i], bm[0][0], bm[0][1]);
                    MMA16816(acc[i][2 * g],     am[0][i], bm[1][0], bm[1][1]);
                    MMA16816(acc[i][2 * g],     am[1][i], bm[0][0], bm[0][1]);
                    MMA16816(acc[i][2 * g],     am[0][i], bm[2][0], bm[2][1]);
                    MMA16816(acc[i][2 * g],     am[1][i], bm[1][0], bm[1][1]);
                    MMA16816(acc[i][2 * g],     am[2][i], bm[0][0], bm[0][1]);
                    MMA16816(acc[i][2 * g + 1], am[0][i], bm[0][2], bm[0][3]);
                    MMA16816(acc[i][2 * g + 1], am[0][i], bm[1][2], bm[1][3]);
                    MMA16816(acc[i][2 * g + 1], am[1][i], bm[0][2], bm[0][3]);
                    MMA16816(acc[i][2 * g + 1], am[0][i], bm[2][2], bm[2][3]);
                    MMA16816(acc[i][2 * g + 1], am[1][i], bm[1][2], bm[1][3]);
                    MMA16816(acc[i][2 * g + 1], am[2][i], bm[0][2], bm[0][3]);
                } else {
                    // 3 products: (0,0) (0,1) (1,0)
                    MMA16816(acc[i][2 * g],     am[0][i], bm[0][0], bm[0][1]);
                    MMA16816(acc[i][2 * g],     am[0][i], bm[1][0], bm[1][1]);
                    MMA16816(acc[i][2 * g],     am[1][i], bm[0][0], bm[0][1]);
                    MMA16816(acc[i][2 * g + 1], am[0][i], bm[0][2], bm[0][3]);
                    MMA16816(acc[i][2 * g + 1], am[0][i], bm[1][2], bm[1][3]);
                    MMA16816(acc[i][2 * g + 1], am[1][i], bm[0][2], bm[0][3]);
                }
            }
        }
        __syncthreads();
    }

    // ---- epilogue: write D tile ----
#pragma unroll
    for (int i = 0; i < 2; i++) {
        int r0 = m0 + wm * 32 + i * 16 + (lane >> 2);
#pragma unroll
        for (int jb = 0; jb < 8; jb++) {
            int col = o0 + wn * 64 + jb * 8 + (lane & 3) * 2;
            *reinterpret_cast<float2*>(&g_pd[(size_t)r0 * 1024 + col]) =
                make_float2(acc[i][jb][0], acc[i][jb][1]);
            *reinterpret_cast<float2*>(&g_pd[(size_t)(r0 + 8) * 1024 + col]) =
                make_float2(acc[i][jb][2], acc[i][jb][3]);
        }
    }
}

static constexpr int SMEM_GRAM = 2 * 6 * MT_BYTES;   // 73728
static constexpr int SMEM_FC   = 2 * 4 * MT_BYTES;   // 49152

// ---------------- fp32 tiled SGEMM for y/base (small) -----------------------
template <int BNT, int TN, bool SUB>
__global__ __launch_bounds__(256) void k_gemm2(
        int aoff, const float* __restrict__ Wa, const float* __restrict__ Wsub,
        int ldw, int Ktot, int ldc, int outsel) {
    __shared__ float As[16][128];
    __shared__ float Bs[16][BNT];
    const float* A = g_cat + aoff;
    const int lda = 512;
    const int m0 = blockIdx.x * 128;
    const int o0 = blockIdx.y * BNT;
    const int tid = threadIdx.x;
    const int trow = tid >> 4;
    const int tcol = tid & 15;

    float acc[8][TN];
#pragma unroll
    for (int i = 0; i < 8; i++)
#pragma unroll
        for (int j = 0; j < TN; j++) acc[i][j] = 0.f;

    const int arow = tid >> 1, akoff = (tid & 1) * 8;
    int brow, bkoff;
    if (BNT == 128) { brow = tid >> 1; bkoff = (tid & 1) * 8; }
    else            { brow = tid >> 2; bkoff = (tid & 3) * 4; }

    const float* bbaseptr = Wa + (size_t)o0 * ldw;

    for (int kt = 0; kt < Ktot; kt += 16) {
        const float* ap = A + (size_t)(m0 + arow) * lda + kt + akoff;
        float4 a0 = *reinterpret_cast<const float4*>(ap);
        float4 a1 = *reinterpret_cast<const float4*>(ap + 4);
        const float* bp = bbaseptr + (size_t)brow * ldw + kt + bkoff;
        float4 b0 = *reinterpret_cast<const float4*>(bp);
        float4 b1;
        if constexpr (BNT == 128) b1 = *reinterpret_cast<const float4*>(bp + 4);
        if constexpr (SUB) {
            const float* sp = Wsub + (size_t)(o0 + brow) * ldw + kt + bkoff;
            float4 s0 = *reinterpret_cast<const float4*>(sp);
            b0.x -= s0.x; b0.y -= s0.y; b0.z -= s0.z; b0.w -= s0.w;
            if constexpr (BNT == 128) {
                float4 s1 = *reinterpret_cast<const float4*>(sp + 4);
                b1.x -= s1.x; b1.y -= s1.y; b1.z -= s1.z; b1.w -= s1.w;
            }
        }
        __syncthreads();
        As[akoff + 0][arow] = a0.x; As[akoff + 1][arow] = a0.y;
        As[akoff + 2][arow] = a0.z; As[akoff + 3][arow] = a0.w;
        As[akoff + 4][arow] = a1.x; As[akoff + 5][arow] = a1.y;
        As[akoff + 6][arow] = a1.z; As[akoff + 7][arow] = a1.w;
        Bs[bkoff + 0][brow] = b0.x; Bs[bkoff + 1][brow] = b0.y;
        Bs[bkoff + 2][brow] = b0.z; Bs[bkoff + 3][brow] = b0.w;
        if constexpr (BNT == 128) {
            Bs[bkoff + 4][brow] = b1.x; Bs[bkoff + 5][brow] = b1.y;
            Bs[bkoff + 6][brow] = b1.z; Bs[bkoff + 7][brow] = b1.w;
        }
        __syncthreads();
#pragma unroll
        for (int kk = 0; kk < 16; kk++) {
            float av[8];
            *reinterpret_cast<float4*>(&av[0]) = *reinterpret_cast<const float4*>(&As[kk][trow * 8]);
            *reinterpret_cast<float4*>(&av[4]) = *reinterpret_cast<const float4*>(&As[kk][trow * 8 + 4]);
            float bv[TN];
            *reinterpret_cast<float4*>(&bv[0]) = *reinterpret_cast<const float4*>(&Bs[kk][tcol * TN]);
            if constexpr (TN == 8)
                *reinterpret_cast<float4*>(&bv[4]) = *reinterpret_cast<const float4*>(&Bs[kk][tcol * TN + 4]);
#pragma unroll
            for (int i = 0; i < 8; i++)
#pragma unroll
                for (int j = 0; j < TN; j++) acc[i][j] = fmaf(av[i], bv[j], acc[i][j]);
        }
    }

    float* cout = outsel ? g_base : g_y;
#pragma unroll
    for (int i = 0; i < 8; i++) {
        int row = m0 + trow * 8 + i;
        float* cp = cout + (size_t)row * ldc + o0 + tcol * TN;
        float4 v0 = make_float4(acc[i][0], acc[i][1], acc[i][2], acc[i][3]);
        *reinterpret_cast<float4*>(cp) = v0;
        if constexpr (TN == 8) {
            float4 v1 = make_float4(acc[i][4], acc[i][5], acc[i][6], acc[i][7]);
            *reinterpret_cast<float4*>(cp + 4) = v1;
        }
    }
}

// ---------------- stage5 column reduce: H (in g_pd) -> max/min/sums ---------
__global__ void k_red5() {
    int b = blockIdx.x >> 2;
    int o = ((blockIdx.x & 3) << 8) + threadIdx.x;   // 256 threads
    const float* p = g_pd + (size_t)b * 1024 * 1024 + o;
    float mx = -1e30f, mn = 1e30f, s = 0.f, s2 = 0.f;
#pragma unroll 8
    for (int n = 0; n < 1024; n++) {
        float v = p[(size_t)n * 1024];
        mx = fmaxf(mx, v); mn = fminf(mn, v);
        s += v; s2 += v * v;
    }
    g_max5[b * 1024 + o] = mx;
    g_min5[b * 1024 + o] = mn;
    g_sumslot[b * 1024 + o] = s;
    g_sqslot[b * 1024 + o]  = s2;
}

// ---------------- stage5 finalize: BN + LReLU on per-(b,o) extremum ---------
__global__ void k_final5(float* __restrict__ out) {
    int i = blockIdx.x * blockDim.x + threadIdx.x;   // 32768
    int o = i & 1023;
    float sc = g_scale[o];
    float v  = (sc >= 0.f) ? g_max5[i] : g_min5[i];
    float hv = fmaf(sc, v, g_bias[o]);
    out[i] = (hv >= 0.f) ? hv : 0.2f * hv;
}

// ---------------- orchestration ---------------------------------------------
extern "C" void kernel_launch(void* const* d_in, const int* in_sizes, int n_in,
                              void* d_out, int out_size) {
    const float* x = (const float*)d_in[0];
    const float *W1 = (const float*)d_in[1],  *G1 = (const float*)d_in[2],  *B1 = (const float*)d_in[3];
    const float *W2 = (const float*)d_in[4],  *G2 = (const float*)d_in[5],  *B2 = (const float*)d_in[6];
    const float *W3 = (const float*)d_in[7],  *G3 = (const float*)d_in[8],  *B3 = (const float*)d_in[9];
    const float *W4 = (const float*)d_in[10], *G4 = (const float*)d_in[11], *B4 = (const float*)d_in[12];
    const float *W5 = (const float*)d_in[13], *G5 = (const float*)d_in[14], *B5 = (const float*)d_in[15];
    float* out = (float*)d_out;

    cudaFuncSetAttribute(k_mma<true>,  cudaFuncAttributeMaxDynamicSharedMemorySize, SMEM_GRAM);
    cudaFuncSetAttribute(k_mma<false>, cudaFuncAttributeMaxDynamicSharedMemorySize, SMEM_FC);

    const float invE = 1.f / (float)((size_t)BN_ * KK);

    k_init<<<256, 256>>>();
    k_convW5<<<2048, 256>>>(W5);

    // ---- Stage 1: C=3, O=64, write cat[0:64) ----
    k_ybase1<<<BN_, 64>>>(x, W1);
    k_knn3<<<BN_ / 128, 128>>>(x);
    k_edge_reduce<<<BN_, 64>>>(64);
    k_stats<<<4, 256>>>(G1, B1, 64, invE);
    k_apply<<<BN_ * 64 / 256, 256>>>(64, 0);

    // ---- Stage 2: in=cat[0:64), C=64, O=64 -> cat[64:128) ----
    k_gemm2<64, 4, false><<<dim3(256, 1), 256>>>(0, W2,      nullptr, 128, 64, 64, 0);
    k_gemm2<64, 4, true ><<<dim3(256, 1), 256>>>(0, W2 + 64, W2,      128, 64, 64, 1);
    k_mma<true><<<dim3(256, 8), 256, SMEM_GRAM>>>(0, 4);
    k_diag<<<BN_ / 256, 256>>>();
    k_select<<<BN_ / 64, 64>>>();
    k_edge_reduce<<<BN_, 64>>>(64);
    k_stats<<<4, 256>>>(G2, B2, 64, invE);
    k_apply<<<BN_ * 64 / 256, 256>>>(64, 64);

    // ---- Stage 3: in=cat[64:128), C=64, O=128 -> cat[128:256) ----
    k_gemm2<128, 8, false><<<dim3(256, 1), 256>>>(64, W3,      nullptr, 128, 64, 128, 0);
    k_gemm2<128, 8, true ><<<dim3(256, 1), 256>>>(64, W3 + 64, W3,      128, 64, 128, 1);
    k_mma<true><<<dim3(256, 8), 256, SMEM_GRAM>>>(64, 4);
    k_diag<<<BN_ / 256, 256>>>();
    k_select<<<BN_ / 64, 64>>>();
    k_edge_reduce<<<BN_, 128>>>(128);
    k_stats<<<4, 256>>>(G3, B3, 128, invE);
    k_apply<<<BN_ * 128 / 256, 256>>>(128, 128);

    // ---- Stage 4: in=cat[128:256), C=128, O=256 -> cat[256:512) ----
    k_gemm2<128, 8, false><<<dim3(256, 2), 256>>>(128, W4,       nullptr, 256, 128, 256, 0);
    k_gemm2<128, 8, true ><<<dim3(256, 2), 256>>>(128, W4 + 128, W4,      256, 128, 256, 1);
    k_mma<true><<<dim3(256, 8), 256, SMEM_GRAM>>>(128, 8);
    k_diag<<<BN_ / 256, 256>>>();
    k_select<<<BN_ / 64, 64>>>();
    k_edge_reduce<<<BN_, 256>>>(256);
    k_stats<<<4, 256>>>(G4, B4, 256, invE);
    k_apply<<<BN_ * 256 / 256, 256>>>(256, 256);

    // ---- Stage 5: FC 512->1024 (mma, 2-way split) + BN + LReLU + max -------
    k_mma<false><<<dim3(256, 8), 256, SMEM_FC>>>(0, 32);
    k_red5<<<128, 256>>>();
    k_stats<<<4, 256>>>(G5, B5, 1024, 1.f / (float)BN_);
    k_final5<<<128, 256>>>(out);
}

// round 8
// speedup vs baseline: 1.9283x; 1.0353x over previous
#include <cuda_runtime.h>
#include <cuda_bf16.h>
#include <cstdint>

#define BB 32
#define NN 1024
#define KK 20
#define BN_ 32768          // BB*NN
#define NSLOT 64

// ---------------- scratch (static __device__, no allocations) ----------------
__device__ float g_cat[BN_ * 512];            // x1|x2|x3|x4 concatenated per point
__device__ __nv_bfloat16 g_cath[BN_ * 512];   // bf16 3-way split of cat: hi
__device__ __nv_bfloat16 g_catm[BN_ * 512];   // mid
__device__ __nv_bfloat16 g_catl[BN_ * 512];   // lo
__device__ __nv_bfloat16 g_wh[1024 * 512];    // W5 hi
__device__ __nv_bfloat16 g_wl[1024 * 512];    // W5 lo
__device__ float g_y[BN_ * 256];         // y = x @ Wa^T
__device__ float g_base[BN_ * 256];      // base = x @ (Wb-Wa)^T
__device__ float g_hmax[BN_ * 256];
__device__ float g_hmin[BN_ * 256];
__device__ float g_pd[(size_t)BB * NN * NN];   // gram matrix / stage5 H (134MB)
__device__ float g_norm[BN_];
__device__ int   g_idx[BN_ * KK];
__device__ float g_sumslot[NSLOT * 1024];
__device__ float g_sqslot[NSLOT * 1024];
__device__ float g_scale[1024];
__device__ float g_bias[1024];
__device__ float g_max5[BB * 1024];
__device__ float g_min5[BB * 1024];

// ---------------- init ------------------------------------------------------
__global__ void k_init() {
    int i = blockIdx.x * blockDim.x + threadIdx.x;
    if (i < NSLOT * 1024) { g_sumslot[i] = 0.f; g_sqslot[i] = 0.f; }
}

// ---------------- split W5 into bf16 hi/lo ----------------------------------
__global__ void k_convW5(const float* __restrict__ W5) {
    int i = blockIdx.x * blockDim.x + threadIdx.x;   // 1024*512
    float v = W5[i];
    __nv_bfloat16 h = __float2bfloat16(v);
    g_wh[i] = h;
    g_wl[i] = __float2bfloat16(v - __bfloat162float(h));
}

// ---------------- stage1 y/base (C=3, O=64) ---------------------------------
__global__ void k_ybase1(const float* __restrict__ x, const float* __restrict__ W) {
    int bn = blockIdx.x;
    int o  = threadIdx.x;   // 64
    __shared__ float xs[3];
    if (o < 3) xs[o] = x[bn * 3 + o];
    __syncthreads();
    const float* w = W + o * 6;
    float y  = w[0] * xs[0] + w[1] * xs[1] + w[2] * xs[2];
    float bs = (w[3] - w[0]) * xs[0] + (w[4] - w[1]) * xs[1] + (w[5] - w[2]) * xs[2];
    g_y[bn * 64 + o]    = y;
    g_base[bn * 64 + o] = bs;
}

// ---------------- branchless sorted-insert chain ----------------------------
#define INSERT20(key, id)                                      \
    if ((key) > vals[KK - 1]) {                                \
        float cv = (key); int ci = (id);                       \
        _Pragma("unroll")                                      \
        for (int _i = 0; _i < KK; _i++) {                      \
            bool sw = cv > vals[_i];                           \
            float tv = vals[_i]; int ti = ids[_i];             \
            vals[_i] = sw ? cv : tv; ids[_i] = sw ? ci : ti;   \
            cv = sw ? tv : cv;  ci = sw ? ti : ci;             \
        }                                                      \
    }

// ---------------- stage-1 kNN: 8 threads/query over xyz in smem -------------
__global__ __launch_bounds__(256) void k_knn3b(const float* __restrict__ xin) {
    __shared__ float scx[1024], scy[1024], scz[1024], snn[1024];
    __shared__ float svals[256][KK];
    __shared__ unsigned short sids[256][KK];
    int t = threadIdx.x;
    int q0 = blockIdx.x * 32;
    int b  = q0 >> 10;
    const float* xb = xin + (size_t)b * 1024 * 3;
    for (int i = t; i < 1024; i += 256) {
        float vx = xb[i * 3], vy = xb[i * 3 + 1], vz = xb[i * 3 + 2];
        scx[i] = vx; scy[i] = vy; scz[i] = vz;
        snn[i] = vx * vx + vy * vy + vz * vz;
    }
    __syncthreads();
    int qi = t >> 3, sub = t & 7;
    int q  = q0 + qi;
    int n  = q & 1023;
    float qx = scx[n], qy = scy[n], qz = scz[n];
    float qq = snn[n];

    float vals[KK]; int ids[KK];
#pragma unroll
    for (int i = 0; i < KK; i++) { vals[i] = -1e30f; ids[i] = 0; }

    for (int i = 0; i < 32; i++) {
        int c = (8 * i + sub) * 4;
#pragma unroll
        for (int kk = 0; kk < 4; kk++) {
            int cc = c + kk;
            float key = 2.f * (qx * scx[cc] + qy * scy[cc] + qz * scz[cc]) - qq - snn[cc];
            INSERT20(key, cc);
        }
    }
#pragma unroll
    for (int k = 0; k < KK; k++) { svals[t][k] = vals[k]; sids[t][k] = (unsigned short)ids[k]; }
    __syncthreads();
    if (sub == 0) {
        int p[8];
#pragma unroll
        for (int j = 0; j < 8; j++) p[j] = 0;
        for (int k = 0; k < KK; k++) {
            float best = -1e31f; int bj = 0;
#pragma unroll
            for (int j = 0; j < 8; j++) {
                float v = svals[t + j][p[j]];
                if (v > best) { best = v; bj = j; }
            }
            g_idx[(size_t)q * KK + k] = (int)sids[t + bj][p[bj]];
            p[bj]++;
        }
    }
}

// ---------------- diag of gram -> candidate norms ---------------------------
__global__ void k_diag() {
    int q = blockIdx.x * blockDim.x + threadIdx.x;
    if (q < BN_) g_norm[q] = g_pd[(size_t)q * NN + (q & 1023)];
}

// ---------------- top-20 select from gram rows: 8 threads/query -------------
__global__ __launch_bounds__(256) void k_sel8() {
    __shared__ float svals[256][KK];
    __shared__ unsigned short sids[256][KK];
    int t = threadIdx.x, qi = t >> 3, sub = t & 7;
    int q = blockIdx.x * 32 + qi;
    int b = q >> 10;
    const float4* row = (const float4*)(g_pd + (size_t)q * NN);
    const float4* nrm = (const float4*)(g_norm + (b << 10));
    float qq = g_norm[q];

    float vals[KK]; int ids[KK];
#pragma unroll
    for (int i = 0; i < KK; i++) { vals[i] = -1e30f; ids[i] = 0; }

    for (int i = 0; i < 32; i++) {
        int j = 8 * i + sub;
        float4 p  = __ldg(row + j);
        float4 n4 = __ldg(nrm + j);
        int c = 4 * j;
        float k0 = 2.f * p.x - qq - n4.x;
        float k1 = 2.f * p.y - qq - n4.y;
        float k2 = 2.f * p.z - qq - n4.z;
        float k3 = 2.f * p.w - qq - n4.w;
        INSERT20(k0, c);
        INSERT20(k1, c + 1);
        INSERT20(k2, c + 2);
        INSERT20(k3, c + 3);
    }
#pragma unroll
    for (int k = 0; k < KK; k++) { svals[t][k] = vals[k]; sids[t][k] = (unsigned short)ids[k]; }
    __syncthreads();
    if (sub == 0) {
        int p[8];
#pragma unroll
        for (int j = 0; j < 8; j++) p[j] = 0;
        for (int k = 0; k < KK; k++) {
            float best = -1e31f; int bj = 0;
#pragma unroll
            for (int j = 0; j < 8; j++) {
                float v = svals[t + j][p[j]];
                if (v > best) { best = v; bj = j; }
            }
            g_idx[(size_t)q * KK + k] = (int)sids[t + bj][p[bj]];
            p[bj]++;
        }
    }
}

// ---------------- gather-reduce over k neighbors ----------------------------
__global__ void k_edge_reduce(int O) {
    int bn = blockIdx.x;
    int o  = threadIdx.x;       // O threads
    int b  = bn >> 10;
    __shared__ int soff[KK];
    if (o < KK) soff[o] = ((b << 10) + g_idx[(size_t)bn * KK + o]) * O;
    __syncthreads();
    float bs = g_base[(size_t)bn * O + o];
    float mx = -1e30f, mn = 1e30f, s = 0.f, s2 = 0.f;
#pragma unroll
    for (int j = 0; j < KK; j++) {
        float v = g_y[soff[j] + o] + bs;
        mx = fmaxf(mx, v); mn = fminf(mn, v);
        s += v; s2 += v * v;
    }
    g_hmax[(size_t)bn * O + o] = mx;
    g_hmin[(size_t)bn * O + o] = mn;
    int slot = bn & (NSLOT - 1);
    atomicAdd(&g_sumslot[slot * 1024 + o], s);
    atomicAdd(&g_sqslot[slot * 1024 + o], s2);
}

// ---------------- BN stats finalize (and rezero slots) ----------------------
__global__ void k_stats(const float* __restrict__ g, const float* __restrict__ bt,
                        int O, float invcnt) {
    int o = blockIdx.x * blockDim.x + threadIdx.x;   // 1024 threads total
    float s = 0.f, s2 = 0.f;
    for (int sl = 0; sl < NSLOT; sl++) {
        s  += g_sumslot[sl * 1024 + o];
        s2 += g_sqslot[sl * 1024 + o];
        g_sumslot[sl * 1024 + o] = 0.f;
        g_sqslot[sl * 1024 + o]  = 0.f;
    }
    if (o < O) {
        float mean = s * invcnt;
        float var  = fmaxf(s2 * invcnt - mean * mean, 0.f);
        float sc   = g[o] * rsqrtf(var + 1e-5f);
        g_scale[o] = sc;
        g_bias[o]  = bt[o] - mean * sc;
    }
}

// -------- apply BN + LReLU to max/min, write cat + 3-way bf16 split ---------
__global__ void k_apply(int O, int coff) {
    int i = blockIdx.x * blockDim.x + threadIdx.x;
    if (i >= BN_ * O) return;
    int o  = i & (O - 1);        // O is a power of two
    int bn = i / O;
    float sc = g_scale[o];
    float v  = (sc >= 0.f) ? g_hmax[i] : g_hmin[i];
    float hv = fmaf(sc, v, g_bias[o]);
    float r  = (hv >= 0.f) ? hv : 0.2f * hv;
    size_t ci = (size_t)bn * 512 + coff + o;
    g_cat[ci] = r;
    __nv_bfloat16 h = __float2bfloat16(r);
    float rm = r - __bfloat162float(h);
    __nv_bfloat16 m = __float2bfloat16(rm);
    g_cath[ci] = h;
    g_catm[ci] = m;
    g_catl[ci] = __float2bfloat16(rm - __bfloat162float(m));
}

// ================= bf16-split tensor-core GEMM (mma.sync, sm_80 path) =======
// D(128x128) = A(128 x Ktot) * B^T.
// GRAM: 3-way split both sides, 6 products (AhBh,AhBm,AmBh,AhBl,AmBm,AlBh).
// else: 2-way split (cat h/m as hi/lo; W5 h/l), 3 products.
// Output: g_pd[(m0+r)*1024 + o0 + c]
#define LDX4(f, addr) \
    asm volatile("ldmatrix.sync.aligned.m8n8.x4.shared.b16 {%0,%1,%2,%3}, [%4];" \
        : "=r"((f)[0]), "=r"((f)[1]), "=r"((f)[2]), "=r"((f)[3]) : "r"(addr))
#define MMA16816(d, a, b0, b1) \
    asm volatile("mma.sync.aligned.m16n8k16.row.col.f32.bf16.bf16.f32 " \
        "{%0,%1,%2,%3},{%4,%5,%6,%7},{%8,%9},{%0,%1,%2,%3};" \
        : "+f"((d)[0]), "+f"((d)[1]), "+f"((d)[2]), "+f"((d)[3]) \
        : "r"((a)[0]), "r"((a)[1]), "r"((a)[2]), "r"((a)[3]), "r"(b0), "r"(b1))

static constexpr int MT_BYTES = 128 * 48;        // one 128x16 bf16 tile, 48B rows

template <bool GRAM>
__global__ __launch_bounds__(256) void k_mma(int aoff, int nchunk) {
    constexpr int NMA  = GRAM ? 3 : 2;
    constexpr int NMB  = GRAM ? 3 : 2;
    constexpr int NMAT = NMA + NMB;
    constexpr int BUFB = NMAT * MT_BYTES;

    extern __shared__ char smem[];
    uint32_t sb;
    asm("{ .reg .u64 t; cvta.to.shared.u64 t, %1; cvt.u32.u64 %0, t; }" : "=r"(sb) : "l"(smem));

    const int tid  = threadIdx.x;
    const int lane = tid & 31;
    const int wid  = tid >> 5;
    const int wm   = wid & 3;          // 4 warps along M
    const int wn   = wid >> 2;         // 2 warps along N
    const int m0   = blockIdx.x * 128;
    const int o0   = blockIdx.y * 128;

    // ---- per-thread cp.async setup (row = tid>>1, half = tid&1) ----
    const int row  = tid >> 1;
    const int half = tid & 1;
    const __nv_bfloat16* gbase[NMAT];
    {
        size_t aio = (size_t)(m0 + row) * 512 + aoff + half * 8;
        gbase[0] = g_cath + aio;
        gbase[1] = g_catm + aio;
        if constexpr (GRAM) gbase[2] = g_catl + aio;
    }
    if constexpr (GRAM) {
        size_t bio = (size_t)((m0 & ~1023) + o0 + row) * 512 + aoff + half * 8;
        gbase[NMA + 0] = g_cath + bio;
        gbase[NMA + 1] = g_catm + bio;
        gbase[NMA + 2] = g_catl + bio;
    } else {
        size_t bio = (size_t)(o0 + row) * 512 + half * 8;
        gbase[NMA + 0] = g_wh + bio;
        gbase[NMA + 1] = g_wl + bio;
    }
    uint32_t soff[NMAT];
#pragma unroll
    for (int j = 0; j < NMAT; j++) soff[j] = sb + j * MT_BYTES + row * 48 + half * 16;

    auto issue = [&](int c, int buf) {
#pragma unroll
        for (int j = 0; j < NMAT; j++) {
            uint32_t sa = soff[j] + buf * BUFB;
            const __nv_bfloat16* gp = gbase[j] + c * 16;
            asm volatile("cp.async.cg.shared.global [%0], [%1], 16;" :: "r"(sa), "l"(gp));
        }
        asm volatile("cp.async.commit_group;");
    };

    // ---- ldmatrix lane addressing ----
    const int arow = (lane & 7) + ((lane >> 3) & 1) * 8;   // A tiles: m-rows
    const int acb  = (lane >> 4) * 16;                     // +16B for k8-15
    const int brow = (lane & 7) + ((lane >> 4) & 1) * 8;   // B tiles: n-rows
    const int bcb  = ((lane >> 3) & 1) * 16;

    float acc[2][8][4];
#pragma unroll
    for (int i = 0; i < 2; i++)
#pragma unroll
        for (int j = 0; j < 8; j++)
#pragma unroll
            for (int q = 0; q < 4; q++) acc[i][j][q] = 0.f;

    issue(0, 0);

    for (int c = 0; c < nchunk; c++) {
        if (c + 1 < nchunk) {
            issue(c + 1, (c + 1) & 1);
            asm volatile("cp.async.wait_group 1;");
        } else {
            asm volatile("cp.async.wait_group 0;");
        }
        __syncthreads();

        const uint32_t bufb = sb + (c & 1) * BUFB;

        uint32_t am[NMA][2][4];
#pragma unroll
        for (int i = 0; i < 2; i++) {
            uint32_t aoffb = (wm * 32 + i * 16 + arow) * 48 + acb;
#pragma unroll
            for (int ma = 0; ma < NMA; ma++)
                LDX4(am[ma][i], bufb + ma * MT_BYTES + aoffb);
        }
#pragma unroll
        for (int g = 0; g < 4; g++) {
            uint32_t boffb = (wn * 64 + g * 16 + brow) * 48 + bcb;
            uint32_t bm[NMB][4];
#pragma unroll
            for (int mb = 0; mb < NMB; mb++)
                LDX4(bm[mb], bufb + (NMA + mb) * MT_BYTES + boffb);
#pragma unroll
            for (int i = 0; i < 2; i++) {
                if constexpr (GRAM) {
                    MMA16816(acc[i][2 * g],     am[0][i], bm[0][0], bm[0][1]);
                    MMA16816(acc[i][2 * g],     am[0][i], bm[1][0], bm[1][1]);
                    MMA16816(acc[i][2 * g],     am[1][i], bm[0][0], bm[0][1]);
                    MMA16816(acc[i][2 * g],     am[0][i], bm[2][0], bm[2][1]);
                    MMA16816(acc[i][2 * g],     am[1][i], bm[1][0], bm[1][1]);
                    MMA16816(acc[i][2 * g],     am[2][i], bm[0][0], bm[0][1]);
                    MMA16816(acc[i][2 * g + 1], am[0][i], bm[0][2], bm[0][3]);
                    MMA16816(acc[i][2 * g + 1], am[0][i], bm[1][2], bm[1][3]);
                    MMA16816(acc[i][2 * g + 1], am[1][i], bm[0][2], bm[0][3]);
                    MMA16816(acc[i][2 * g + 1], am[0][i], bm[2][2], bm[2][3]);
                    MMA16816(acc[i][2 * g + 1], am[1][i], bm[1][2], bm[1][3]);
                    MMA16816(acc[i][2 * g + 1], am[2][i], bm[0][2], bm[0][3]);
                } else {
                    MMA16816(acc[i][2 * g],     am[0][i], bm[0][0], bm[0][1]);
                    MMA16816(acc[i][2 * g],     am[0][i], bm[1][0], bm[1][1]);
                    MMA16816(acc[i][2 * g],     am[1][i], bm[0][0], bm[0][1]);
                    MMA16816(acc[i][2 * g + 1], am[0][i], bm[0][2], bm[0][3]);
                    MMA16816(acc[i][2 * g + 1], am[0][i], bm[1][2], bm[1][3]);
                    MMA16816(acc[i][2 * g + 1], am[1][i], bm[0][2], bm[0][3]);
                }
            }
        }
        __syncthreads();
    }

    // ---- epilogue: write D tile ----
#pragma unroll
    for (int i = 0; i < 2; i++) {
        int r0 = m0 + wm * 32 + i * 16 + (lane >> 2);
#pragma unroll
        for (int jb = 0; jb < 8; jb++) {
            int col = o0 + wn * 64 + jb * 8 + (lane & 3) * 2;
            *reinterpret_cast<float2*>(&g_pd[(size_t)r0 * 1024 + col]) =
                make_float2(acc[i][jb][0], acc[i][jb][1]);
            *reinterpret_cast<float2*>(&g_pd[(size_t)(r0 + 8) * 1024 + col]) =
                make_float2(acc[i][jb][2], acc[i][jb][3]);
        }
    }
}

static constexpr int SMEM_GRAM = 2 * 6 * MT_BYTES;   // 73728
static constexpr int SMEM_FC   = 2 * 4 * MT_BYTES;   // 49152

// ---------------- fp32 tiled SGEMM for y/base (small) -----------------------
template <int BNT, int TN, bool SUB>
__global__ __launch_bounds__(256) void k_gemm2(
        int aoff, const float* __restrict__ Wa, const float* __restrict__ Wsub,
        int ldw, int Ktot, int ldc, int outsel) {
    __shared__ float As[16][128];
    __shared__ float Bs[16][BNT];
    const float* A = g_cat + aoff;
    const int lda = 512;
    const int m0 = blockIdx.x * 128;
    const int o0 = blockIdx.y * BNT;
    const int tid = threadIdx.x;
    const int trow = tid >> 4;
    const int tcol = tid & 15;

    float acc[8][TN];
#pragma unroll
    for (int i = 0; i < 8; i++)
#pragma unroll
        for (int j = 0; j < TN; j++) acc[i][j] = 0.f;

    const int arow = tid >> 1, akoff = (tid & 1) * 8;
    int brow, bkoff;
    if (BNT == 128) { brow = tid >> 1; bkoff = (tid & 1) * 8; }
    else            { brow = tid >> 2; bkoff = (tid & 3) * 4; }

    const float* bbaseptr = Wa + (size_t)o0 * ldw;

    for (int kt = 0; kt < Ktot; kt += 16) {
        const float* ap = A + (size_t)(m0 + arow) * lda + kt + akoff;
        float4 a0 = *reinterpret_cast<const float4*>(ap);
        float4 a1 = *reinterpret_cast<const float4*>(ap + 4);
        const float* bp = bbaseptr + (size_t)brow * ldw + kt + bkoff;
        float4 b0 = *reinterpret_cast<const float4*>(bp);
        float4 b1;
        if constexpr (BNT == 128) b1 = *reinterpret_cast<const float4*>(bp + 4);
        if constexpr (SUB) {
            const float* sp = Wsub + (size_t)(o0 + brow) * ldw + kt + bkoff;
            float4 s0 = *reinterpret_cast<const float4*>(sp);
            b0.x -= s0.x; b0.y -= s0.y; b0.z -= s0.z; b0.w -= s0.w;
            if constexpr (BNT == 128) {
                float4 s1 = *reinterpret_cast<const float4*>(sp + 4);
                b1.x -= s1.x; b1.y -= s1.y; b1.z -= s1.z; b1.w -= s1.w;
            }
        }
        __syncthreads();
        As[akoff + 0][arow] = a0.x; As[akoff + 1][arow] = a0.y;
        As[akoff + 2][arow] = a0.z; As[akoff + 3][arow] = a0.w;
        As[akoff + 4][arow] = a1.x; As[akoff + 5][arow] = a1.y;
        As[akoff + 6][arow] = a1.z; As[akoff + 7][arow] = a1.w;
        Bs[bkoff + 0][brow] = b0.x; Bs[bkoff + 1][brow] = b0.y;
        Bs[bkoff + 2][brow] = b0.z; Bs[bkoff + 3][brow] = b0.w;
        if constexpr (BNT == 128) {
            Bs[bkoff + 4][brow] = b1.x; Bs[bkoff + 5][brow] = b1.y;
            Bs[bkoff + 6][brow] = b1.z; Bs[bkoff + 7][brow] = b1.w;
        }
        __syncthreads();
#pragma unroll
        for (int kk = 0; kk < 16; kk++) {
            float av[8];
            *reinterpret_cast<float4*>(&av[0]) = *reinterpret_cast<const float4*>(&As[kk][trow * 8]);
            *reinterpret_cast<float4*>(&av[4]) = *reinterpret_cast<const float4*>(&As[kk][trow * 8 + 4]);
            float bv[TN];
            *reinterpret_cast<float4*>(&bv[0]) = *reinterpret_cast<const float4*>(&Bs[kk][tcol * TN]);
            if constexpr (TN == 8)
                *reinterpret_cast<float4*>(&bv[4]) = *reinterpret_cast<const float4*>(&Bs[kk][tcol * TN + 4]);
#pragma unroll
            for (int i = 0; i < 8; i++)
#pragma unroll
                for (int j = 0; j < TN; j++) acc[i][j] = fmaf(av[i], bv[j], acc[i][j]);
        }
    }

    float* cout = outsel ? g_base : g_y;
#pragma unroll
    for (int i = 0; i < 8; i++) {
        int row = m0 + trow * 8 + i;
        float* cp = cout + (size_t)row * ldc + o0 + tcol * TN;
        float4 v0 = make_float4(acc[i][0], acc[i][1], acc[i][2], acc[i][3]);
        *reinterpret_cast<float4*>(cp) = v0;
        if constexpr (TN == 8) {
            float4 v1 = make_float4(acc[i][4], acc[i][5], acc[i][6], acc[i][7]);
            *reinterpret_cast<float4*>(cp + 4) = v1;
        }
    }
}

// ---------------- stage5 column reduce: H (in g_pd) -> max/min/sums ---------
__global__ void k_red5() {
    int b = blockIdx.x >> 2;
    int o = ((blockIdx.x & 3) << 8) + threadIdx.x;   // 256 threads
    const float* p = g_pd + (size_t)b * 1024 * 1024 + o;
    float mx = -1e30f, mn = 1e30f, s = 0.f, s2 = 0.f;
#pragma unroll 8
    for (int n = 0; n < 1024; n++) {
        float v = p[(size_t)n * 1024];
        mx = fmaxf(mx, v); mn = fminf(mn, v);
        s += v; s2 += v * v;
    }
    g_max5[b * 1024 + o] = mx;
    g_min5[b * 1024 + o] = mn;
    g_sumslot[b * 1024 + o] = s;
    g_sqslot[b * 1024 + o]  = s2;
}

// ---------------- stage5 finalize: BN + LReLU on per-(b,o) extremum ---------
__global__ void k_final5(float* __restrict__ out) {
    int i = blockIdx.x * blockDim.x + threadIdx.x;   // 32768
    int o = i & 1023;
    float sc = g_scale[o];
    float v  = (sc >= 0.f) ? g_max5[i] : g_min5[i];
    float hv = fmaf(sc, v, g_bias[o]);
    out[i] = (hv >= 0.f) ? hv : 0.2f * hv;
}

// ---------------- orchestration ---------------------------------------------
extern "C" void kernel_launch(void* const* d_in, const int* in_sizes, int n_in,
                              void* d_out, int out_size) {
    const float* x = (const float*)d_in[0];
    const float *W1 = (const float*)d_in[1],  *G1 = (const float*)d_in[2],  *B1 = (const float*)d_in[3];
    const float *W2 = (const float*)d_in[4],  *G2 = (const float*)d_in[5],  *B2 = (const float*)d_in[6];
    const float *W3 = (const float*)d_in[7],  *G3 = (const float*)d_in[8],  *B3 = (const float*)d_in[9];
    const float *W4 = (const float*)d_in[10], *G4 = (const float*)d_in[11], *B4 = (const float*)d_in[12];
    const float *W5 = (const float*)d_in[13], *G5 = (const float*)d_in[14], *B5 = (const float*)d_in[15];
    float* out = (float*)d_out;

    cudaFuncSetAttribute(k_mma<true>,  cudaFuncAttributeMaxDynamicSharedMemorySize, SMEM_GRAM);
    cudaFuncSetAttribute(k_mma<false>, cudaFuncAttributeMaxDynamicSharedMemorySize, SMEM_FC);

    const float invE = 1.f / (float)((size_t)BN_ * KK);

    k_init<<<256, 256>>>();
    k_convW5<<<2048, 256>>>(W5);

    // ---- Stage 1: C=3, O=64, write cat[0:64) ----
    k_ybase1<<<BN_, 64>>>(x, W1);
    k_knn3b<<<BN_ / 32, 256>>>(x);
    k_edge_reduce<<<BN_, 64>>>(64);
    k_stats<<<4, 256>>>(G1, B1, 64, invE);
    k_apply<<<BN_ * 64 / 256, 256>>>(64, 0);

    // ---- Stage 2: in=cat[0:64), C=64, O=64 -> cat[64:128) ----
    k_gemm2<64, 4, false><<<dim3(256, 1), 256>>>(0, W2,      nullptr, 128, 64, 64, 0);
    k_gemm2<64, 4, true ><<<dim3(256, 1), 256>>>(0, W2 + 64, W2,      128, 64, 64, 1);
    k_mma<true><<<dim3(256, 8), 256, SMEM_GRAM>>>(0, 4);
    k_diag<<<BN_ / 256, 256>>>();
    k_sel8<<<BN_ / 32, 256>>>();
    k_edge_reduce<<<BN_, 64>>>(64);
    k_stats<<<4, 256>>>(G2, B2, 64, invE);
    k_apply<<<BN_ * 64 / 256, 256>>>(64, 64);

    // ---- Stage 3: in=cat[64:128), C=64, O=128 -> cat[128:256) ----
    k_gemm2<128, 8, false><<<dim3(256, 1), 256>>>(64, W3,      nullptr, 128, 64, 128, 0);
    k_gemm2<128, 8, true ><<<dim3(256, 1), 256>>>(64, W3 + 64, W3,      128, 64, 128, 1);
    k_mma<true><<<dim3(256, 8), 256, SMEM_GRAM>>>(64, 4);
    k_diag<<<BN_ / 256, 256>>>();
    k_sel8<<<BN_ / 32, 256>>>();
    k_edge_reduce<<<BN_, 128>>>(128);
    k_stats<<<4, 256>>>(G3, B3, 128, invE);
    k_apply<<<BN_ * 128 / 256, 256>>>(128, 128);

    // ---- Stage 4: in=cat[128:256), C=128, O=256 -> cat[256:512) ----
    k_gemm2<128, 8, false><<<dim3(256, 2), 256>>>(128, W4,       nullptr, 256, 128, 256, 0);
    k_gemm2<128, 8, true ><<<dim3(256, 2), 256>>>(128, W4 + 128, W4,      256, 128, 256, 1);
    k_mma<true><<<dim3(256, 8), 256, SMEM_GRAM>>>(128, 8);
    k_diag<<<BN_ / 256, 256>>>();
    k_sel8<<<BN_ / 32, 256>>>();
    k_edge_reduce<<<BN_, 256>>>(256);
    k_stats<<<4, 256>>>(G4, B4, 256, invE);
    k_apply<<<BN_ * 256 / 256, 256>>>(256, 256);

    // ---- Stage 5: FC 512->1024 (mma, 2-way split) + BN + LReLU + max -------
    k_mma<false><<<dim3(256, 8), 256, SMEM_FC>>>(0, 32);
    k_red5<<<128, 256>>>();
    k_stats<<<4, 256>>>(G5, B5, 1024, 1.f / (float)BN_);
    k_final5<<<128, 256>>>(out);
}

// round 12
// speedup vs baseline: 1.9557x; 1.0142x over previous
#include <cuda_runtime.h>
#include <cuda_bf16.h>
#include <cstdint>

#define BB 32
#define NN 1024
#define KK 20
#define BN_ 32768          // BB*NN
#define NSLOT 64

// ---------------- scratch (static __device__, no allocations) ----------------
__device__ float g_cat[BN_ * 512];            // x1|x2|x3|x4 concatenated per point
__device__ __nv_bfloat16 g_cath[BN_ * 512];   // bf16 3-way split of cat: hi
__device__ __nv_bfloat16 g_catm[BN_ * 512];   // mid
__device__ __nv_bfloat16 g_catl[BN_ * 512];   // lo
__device__ __nv_bfloat16 g_wh[1024 * 512];    // W5 hi
__device__ __nv_bfloat16 g_wl[1024 * 512];    // W5 lo
__device__ float g_y[BN_ * 256];         // y = x @ Wa^T
__device__ float g_base[BN_ * 256];      // base = x @ (Wb-Wa)^T
__device__ float g_hmax[BN_ * 256];
__device__ float g_hmin[BN_ * 256];
__device__ float g_pd[(size_t)BB * NN * NN];   // gram matrix / stage5 H (134MB)
__device__ float g_norm[BN_];
__device__ int   g_idx[BN_ * KK];
__device__ float g_sumslot[NSLOT * 1024];
__device__ float g_sqslot[NSLOT * 1024];
__device__ float g_scale[1024];
__device__ float g_bias[1024];
__device__ float g_max5[BB * 1024];
__device__ float g_min5[BB * 1024];

// ---------------- init ------------------------------------------------------
__global__ void k_init() {
    int i = blockIdx.x * blockDim.x + threadIdx.x;
    if (i < NSLOT * 1024) { g_sumslot[i] = 0.f; g_sqslot[i] = 0.f; }
}

// ---------------- split W5 into bf16 hi/lo ----------------------------------
__global__ void k_convW5(const float* __restrict__ W5) {
    int i = blockIdx.x * blockDim.x + threadIdx.x;   // 1024*512
    float v = W5[i];
    __nv_bfloat16 h = __float2bfloat16(v);
    g_wh[i] = h;
    g_wl[i] = __float2bfloat16(v - __bfloat162float(h));
}

// ---------------- stage1 y/base (C=3, O=64) ---------------------------------
__global__ void k_ybase1(const float* __restrict__ x, const float* __restrict__ W) {
    int bn = blockIdx.x;
    int o  = threadIdx.x;   // 64
    __shared__ float xs[3];
    if (o < 3) xs[o] = x[bn * 3 + o];
    __syncthreads();
    const float* w = W + o * 6;
    float y  = w[0] * xs[0] + w[1] * xs[1] + w[2] * xs[2];
    float bs = (w[3] - w[0]) * xs[0] + (w[4] - w[1]) * xs[1] + (w[5] - w[2]) * xs[2];
    g_y[bn * 64 + o]    = y;
    g_base[bn * 64 + o] = bs;
}

// ---------------- branchless sorted-insert chain ----------------------------
#define INSERT20(key, id)                                      \
    if ((key) > vals[KK - 1]) {                                \
        float cv = (key); int ci = (id);                       \
        _Pragma("unroll")                                      \
        for (int _i = 0; _i < KK; _i++) {                      \
            bool sw = cv > vals[_i];                           \
            float tv = vals[_i]; int ti = ids[_i];             \
            vals[_i] = sw ? cv : tv; ids[_i] = sw ? ci : ti;   \
            cv = sw ? tv : cv;  ci = sw ? ti : ci;             \
        }                                                      \
    }

// ---------------- stage-1 kNN: 8 threads/query over xyz in smem -------------
__global__ __launch_bounds__(256) void k_knn3b(const float* __restrict__ xin) {
    __shared__ float scx[1024], scy[1024], scz[1024], snn[1024];
    __shared__ float svals[256][KK];
    __shared__ unsigned short sids[256][KK];
    int t = threadIdx.x;
    int q0 = blockIdx.x * 32;
    int b  = q0 >> 10;
    const float* xb = xin + (size_t)b * 1024 * 3;
    for (int i = t; i < 1024; i += 256) {
        float vx = xb[i * 3], vy = xb[i * 3 + 1], vz = xb[i * 3 + 2];
        scx[i] = vx; scy[i] = vy; scz[i] = vz;
        snn[i] = vx * vx + vy * vy + vz * vz;
    }
    __syncthreads();
    int qi = t >> 3, sub = t & 7;
    int q  = q0 + qi;
    int n  = q & 1023;
    float qx = scx[n], qy = scy[n], qz = scz[n];
    float qq = snn[n];

    float vals[KK]; int ids[KK];
#pragma unroll
    for (int i = 0; i < KK; i++) { vals[i] = -1e30f; ids[i] = 0; }

    for (int i = 0; i < 32; i++) {
        int c = (8 * i + sub) * 4;
#pragma unroll
        for (int kk = 0; kk < 4; kk++) {
            int cc = c + kk;
            float key = 2.f * (qx * scx[cc] + qy * scy[cc] + qz * scz[cc]) - qq - snn[cc];
            INSERT20(key, cc);
        }
    }
#pragma unroll
    for (int k = 0; k < KK; k++) { svals[t][k] = vals[k]; sids[t][k] = (unsigned short)ids[k]; }
    __syncthreads();
    if (sub == 0) {
        int p[8];
#pragma unroll
        for (int j = 0; j < 8; j++) p[j] = 0;
        for (int k = 0; k < KK; k++) {
            float best = -1e31f; int bj = 0;
#pragma unroll
            for (int j = 0; j < 8; j++) {
                float v = svals[t + j][p[j]];
                if (v > best) { best = v; bj = j; }
            }
            g_idx[(size_t)q * KK + k] = (int)sids[t + bj][p[bj]];
            p[bj]++;
        }
    }
}

// ---------------- diag of gram -> candidate norms ---------------------------
__global__ void k_diag() {
    int q = blockIdx.x * blockDim.x + threadIdx.x;
    if (q < BN_) g_norm[q] = g_pd[(size_t)q * NN + (q & 1023)];
}

// ---------------- top-20 select from gram rows: 8 threads/query -------------
__global__ __launch_bounds__(256) void k_sel8() {
    __shared__ float svals[256][KK];
    __shared__ unsigned short sids[256][KK];
    int t = threadIdx.x, qi = t >> 3, sub = t & 7;
    int q = blockIdx.x * 32 + qi;
    int b = q >> 10;
    const float4* row = (const float4*)(g_pd + (size_t)q * NN);
    const float4* nrm = (const float4*)(g_norm + (b << 10));
    float qq = g_norm[q];

    float vals[KK]; int ids[KK];
#pragma unroll
    for (int i = 0; i < KK; i++) { vals[i] = -1e30f; ids[i] = 0; }

    for (int i = 0; i < 32; i++) {
        int j = 8 * i + sub;
        float4 p  = __ldg(row + j);
        float4 n4 = __ldg(nrm + j);
        int c = 4 * j;
        float k0 = 2.f * p.x - qq - n4.x;
        float k1 = 2.f * p.y - qq - n4.y;
        float k2 = 2.f * p.z - qq - n4.z;
        float k3 = 2.f * p.w - qq - n4.w;
        INSERT20(k0, c);
        INSERT20(k1, c + 1);
        INSERT20(k2, c + 2);
        INSERT20(k3, c + 3);
    }
#pragma unroll
    for (int k = 0; k < KK; k++) { svals[t][k] = vals[k]; sids[t][k] = (unsigned short)ids[k]; }
    __syncthreads();
    if (sub == 0) {
        int p[8];
#pragma unroll
        for (int j = 0; j < 8; j++) p[j] = 0;
        for (int k = 0; k < KK; k++) {
            float best = -1e31f; int bj = 0;
#pragma unroll
            for (int j = 0; j < 8; j++) {
                float v = svals[t + j][p[j]];
                if (v > best) { best = v; bj = j; }
            }
            g_idx[(size_t)q * KK + k] = (int)sids[t + bj][p[bj]];
            p[bj]++;
        }
    }
}

// ---------------- gather-reduce over k neighbors ----------------------------
__global__ void k_edge_reduce(int O) {
    int bn = blockIdx.x;
    int o  = threadIdx.x;       // O threads
    int b  = bn >> 10;
    __shared__ int soff[KK];
    if (o < KK) soff[o] = ((b << 10) + g_idx[(size_t)bn * KK + o]) * O;
    __syncthreads();
    float bs = g_base[(size_t)bn * O + o];
    float mx = -1e30f, mn = 1e30f, s = 0.f, s2 = 0.f;
#pragma unroll
    for (int j = 0; j < KK; j++) {
        float v = g_y[soff[j] + o] + bs;
        mx = fmaxf(mx, v); mn = fminf(mn, v);
        s += v; s2 += v * v;
    }
    g_hmax[(size_t)bn * O + o] = mx;
    g_hmin[(size_t)bn * O + o] = mn;
    int slot = bn & (NSLOT - 1);
    atomicAdd(&g_sumslot[slot * 1024 + o], s);
    atomicAdd(&g_sqslot[slot * 1024 + o], s2);
}

// ---------------- BN stats finalize (and rezero slots) ----------------------
__global__ void k_stats(const float* __restrict__ g, const float* __restrict__ bt,
                        int O, float invcnt) {
    int o = blockIdx.x * blockDim.x + threadIdx.x;   // 1024 threads total
    float s = 0.f, s2 = 0.f;
    for (int sl = 0; sl < NSLOT; sl++) {
        s  += g_sumslot[sl * 1024 + o];
        s2 += g_sqslot[sl * 1024 + o];
        g_sumslot[sl * 1024 + o] = 0.f;
        g_sqslot[sl * 1024 + o]  = 0.f;
    }
    if (o < O) {
        float mean = s * invcnt;
        float var  = fmaxf(s2 * invcnt - mean * mean, 0.f);
        float sc   = g[o] * rsqrtf(var + 1e-5f);
        g_scale[o] = sc;
        g_bias[o]  = bt[o] - mean * sc;
    }
}

// -------- apply BN + LReLU to max/min, write cat + 3-way bf16 split ---------
__global__ void k_apply(int O, int coff) {
    int i = blockIdx.x * blockDim.x + threadIdx.x;
    if (i >= BN_ * O) return;
    int o  = i & (O - 1);        // O is a power of two
    int bn = i / O;
    float sc = g_scale[o];
    float v  = (sc >= 0.f) ? g_hmax[i] : g_hmin[i];
    float hv = fmaf(sc, v, g_bias[o]);
    float r  = (hv >= 0.f) ? hv : 0.2f * hv;
    size_t ci = (size_t)bn * 512 + coff + o;
    g_cat[ci] = r;
    __nv_bfloat16 h = __float2bfloat16(r);
    float rm = r - __bfloat162float(h);
    __nv_bfloat16 m = __float2bfloat16(rm);
    g_cath[ci] = h;
    g_catm[ci] = m;
    g_catl[ci] = __float2bfloat16(rm - __bfloat162float(m));
}

// ================= bf16-split tensor-core GEMM (mma.sync, sm_80 path) =======
#define LDX4(f, addr) \
    asm volatile("ldmatrix.sync.aligned.m8n8.x4.shared.b16 {%0,%1,%2,%3}, [%4];" \
        : "=r"((f)[0]), "=r"((f)[1]), "=r"((f)[2]), "=r"((f)[3]) : "r"(addr))
#define MMA16816(d, a, b0, b1) \
    asm volatile("mma.sync.aligned.m16n8k16.row.col.f32.bf16.bf16.f32 " \
        "{%0,%1,%2,%3},{%4,%5,%6,%7},{%8,%9},{%0,%1,%2,%3};" \
        : "+f"((d)[0]), "+f"((d)[1]), "+f"((d)[2]), "+f"((d)[3]) \
        : "r"((a)[0]), "r"((a)[1]), "r"((a)[2]), "r"((a)[3]), "r"(b0), "r"(b1))

static constexpr int MT_BYTES = 128 * 48;        // one 128x16 bf16 tile, 48B rows

template <bool GRAM>
__global__ __launch_bounds__(256) void k_mma(int aoff, int nchunk) {
    constexpr int NMA  = GRAM ? 3 : 2;
    constexpr int NMB  = GRAM ? 3 : 2;
    constexpr int NMAT = NMA + NMB;
    constexpr int BUFB = NMAT * MT_BYTES;

    extern __shared__ char smem[];
    uint32_t sb;
    asm("{ .reg .u64 t; cvta.to.shared.u64 t, %1; cvt.u32.u64 %0, t; }" : "=r"(sb) : "l"(smem));

    const int tid  = threadIdx.x;
    const int lane = tid & 31;
    const int wid  = tid >> 5;
    const int wm   = wid & 3;          // 4 warps along M
    const int wn   = wid >> 2;         // 2 warps along N
    const int m0   = blockIdx.x * 128;
    const int o0   = blockIdx.y * 128;

    const int row  = tid >> 1;
    const int half = tid & 1;
    const __nv_bfloat16* gbase[NMAT];
    {
        size_t aio = (size_t)(m0 + row) * 512 + aoff + half * 8;
        gbase[0] = g_cath + aio;
        gbase[1] = g_catm + aio;
        if constexpr (GRAM) gbase[2] = g_catl + aio;
    }
    if constexpr (GRAM) {
        size_t bio = (size_t)((m0 & ~1023) + o0 + row) * 512 + aoff + half * 8;
        gbase[NMA + 0] = g_cath + bio;
        gbase[NMA + 1] = g_catm + bio;
        gbase[NMA + 2] = g_catl + bio;
    } else {
        size_t bio = (size_t)(o0 + row) * 512 + half * 8;
        gbase[NMA + 0] = g_wh + bio;
        gbase[NMA + 1] = g_wl + bio;
    }
    uint32_t soff[NMAT];
#pragma unroll
    for (int j = 0; j < NMAT; j++) soff[j] = sb + j * MT_BYTES + row * 48 + half * 16;

    auto issue = [&](int c, int buf) {
#pragma unroll
        for (int j = 0; j < NMAT; j++) {
            uint32_t sa = soff[j] + buf * BUFB;
            const __nv_bfloat16* gp = gbase[j] + c * 16;
            asm volatile("cp.async.cg.shared.global [%0], [%1], 16;" :: "r"(sa), "l"(gp));
        }
        asm volatile("cp.async.commit_group;");
    };

    const int arow = (lane & 7) + ((lane >> 3) & 1) * 8;   // A tiles: m-rows
    const int acb  = (lane >> 4) * 16;                     // +16B for k8-15
    const int brow = (lane & 7) + ((lane >> 4) & 1) * 8;   // B tiles: n-rows
    const int bcb  = ((lane >> 3) & 1) * 16;

    float acc[2][8][4];
#pragma unroll
    for (int i = 0; i < 2; i++)
#pragma unroll
        for (int j = 0; j < 8; j++)
#pragma unroll
            for (int q = 0; q < 4; q++) acc[i][j][q] = 0.f;

    issue(0, 0);

    for (int c = 0; c < nchunk; c++) {
        if (c + 1 < nchunk) {
            issue(c + 1, (c + 1) & 1);
            asm volatile("cp.async.wait_group 1;");
        } else {
            asm volatile("cp.async.wait_group 0;");
        }
        __syncthreads();

        const uint32_t bufb = sb + (c & 1) * BUFB;

        uint32_t am[NMA][2][4];
#pragma unroll
        for (int i = 0; i < 2; i++) {
            uint32_t aoffb = (wm * 32 + i * 16 + arow) * 48 + acb;
#pragma unroll
            for (int ma = 0; ma < NMA; ma++)
                LDX4(am[ma][i], bufb + ma * MT_BYTES + aoffb);
        }
#pragma unroll
        for (int g = 0; g < 4; g++) {
            uint32_t boffb = (wn * 64 + g * 16 + brow) * 48 + bcb;
            uint32_t bm[NMB][4];
#pragma unroll
            for (int mb = 0; mb < NMB; mb++)
                LDX4(bm[mb], bufb + (NMA + mb) * MT_BYTES + boffb);
#pragma unroll
            for (int i = 0; i < 2; i++) {
                if constexpr (GRAM) {
                    MMA16816(acc[i][2 * g],     am[0][i], bm[0][0], bm[0][1]);
                    MMA16816(acc[i][2 * g],     am[0][i], bm[1][0], bm[1][1]);
                    MMA16816(acc[i][2 * g],     am[1][i], bm[0][0], bm[0][1]);
                    MMA16816(acc[i][2 * g],     am[0][i], bm[2][0], bm[2][1]);
                    MMA16816(acc[i][2 * g],     am[1][i], bm[1][0], bm[1][1]);
                    MMA16816(acc[i][2 * g],     am[2][i], bm[0][0], bm[0][1]);
                    MMA16816(acc[i][2 * g + 1], am[0][i], bm[0][2], bm[0][3]);
                    MMA16816(acc[i][2 * g + 1], am[0][i], bm[1][2], bm[1][3]);
                    MMA16816(acc[i][2 * g + 1], am[1][i], bm[0][2], bm[0][3]);
                    MMA16816(acc[i][2 * g + 1], am[0][i], bm[2][2], bm[2][3]);
                    MMA16816(acc[i][2 * g + 1], am[1][i], bm[1][2], bm[1][3]);
                    MMA16816(acc[i][2 * g + 1], am[2][i], bm[0][2], bm[0][3]);
                } else {
                    MMA16816(acc[i][2 * g],     am[0][i], bm[0][0], bm[0][1]);
                    MMA16816(acc[i][2 * g],     am[0][i], bm[1][0], bm[1][1]);
                    MMA16816(acc[i][2 * g],     am[1][i], bm[0][0], bm[0][1]);
                    MMA16816(acc[i][2 * g + 1], am[0][i], bm[0][2], bm[0][3]);
                    MMA16816(acc[i][2 * g + 1], am[0][i], bm[1][2], bm[1][3]);
                    MMA16816(acc[i][2 * g + 1], am[1][i], bm[0][2], bm[0][3]);
                }
            }
        }
        __syncthreads();
    }

#pragma unroll
    for (int i = 0; i < 2; i++) {
        int r0 = m0 + wm * 32 + i * 16 + (lane >> 2);
#pragma unroll
        for (int jb = 0; jb < 8; jb++) {
            int col = o0 + wn * 64 + jb * 8 + (lane & 3) * 2;
            *reinterpret_cast<float2*>(&g_pd[(size_t)r0 * 1024 + col]) =
                make_float2(acc[i][jb][0], acc[i][jb][1]);
            *reinterpret_cast<float2*>(&g_pd[(size_t)(r0 + 8) * 1024 + col]) =
                make_float2(acc[i][jb][2], acc[i][jb][3]);
        }
    }
}

static constexpr int SMEM_GRAM = 2 * 6 * MT_BYTES;   // 73728
static constexpr int SMEM_FC   = 2 * 4 * MT_BYTES;   // 49152

// ------- merged fp32 SGEMM for y AND base: blockIdx.z selects output --------
// z=0: C = A @ W[:, 0:C]^T -> g_y ; z=1: C = A @ (W[:, C:2C]-W[:, 0:C])^T -> g_base
template <int BNT, int TN>
__global__ __launch_bounds__(256) void k_gemm2m(
        int aoff, const float* __restrict__ W, int ldw, int Ktot, int ldc) {
    __shared__ float As[16][128];
    __shared__ float Bs[16][BNT];
    const float* A = g_cat + aoff;
    const int lda = 512;
    const int m0 = blockIdx.x * 128;
    const int o0 = blockIdx.y * BNT;
    const bool sub = (blockIdx.z != 0);
    const int coff = sub ? (ldw >> 1) : 0;   // second half of W rows for base
    const int tid = threadIdx.x;
    const int trow = tid >> 4;
    const int tcol = tid & 15;

    float acc[8][TN];
#pragma unroll
    for (int i = 0; i < 8; i++)
#pragma unroll
        for (int j = 0; j < TN; j++) acc[i][j] = 0.f;

    const int arow = tid >> 1, akoff = (tid & 1) * 8;
    int brow, bkoff;
    if (BNT == 128) { brow = tid >> 1; bkoff = (tid & 1) * 8; }
    else            { brow = tid >> 2; bkoff = (tid & 3) * 4; }

    const float* bbaseptr = W + (size_t)o0 * ldw;

    for (int kt = 0; kt < Ktot; kt += 16) {
        const float* ap = A + (size_t)(m0 + arow) * lda + kt + akoff;
        float4 a0 = *reinterpret_cast<const float4*>(ap);
        float4 a1 = *reinterpret_cast<const float4*>(ap + 4);
        const float* bp = bbaseptr + (size_t)brow * ldw + coff + kt + bkoff;
        float4 b0 = *reinterpret_cast<const float4*>(bp);
        float4 b1;
        if constexpr (BNT == 128) b1 = *reinterpret_cast<const float4*>(bp + 4);
        if (sub) {
            const float* sp = bbaseptr + (size_t)brow * ldw + kt + bkoff;
            float4 s0 = *reinterpret_cast<const float4*>(sp);
            b0.x -= s0.x; b0.y -= s0.y; b0.z -= s0.z; b0.w -= s0.w;
            if constexpr (BNT == 128) {
                float4 s1 = *reinterpret_cast<const float4*>(sp + 4);
                b1.x -= s1.x; b1.y -= s1.y; b1.z -= s1.z; b1.w -= s1.w;
            }
        }
        __syncthreads();
        As[akoff + 0][arow] = a0.x; As[akoff + 1][arow] = a0.y;
        As[akoff + 2][arow] = a0.z; As[akoff + 3][arow] = a0.w;
        As[akoff + 4][arow] = a1.x; As[akoff + 5][arow] = a1.y;
        As[akoff + 6][arow] = a1.z; As[akoff + 7][arow] = a1.w;
        Bs[bkoff + 0][brow] = b0.x; Bs[bkoff + 1][brow] = b0.y;
        Bs[bkoff + 2][brow] = b0.z; Bs[bkoff + 3][brow] = b0.w;
        if constexpr (BNT == 128) {
            Bs[bkoff + 4][brow] = b1.x; Bs[bkoff + 5][brow] = b1.y;
            Bs[bkoff + 6][brow] = b1.z; Bs[bkoff + 7][brow] = b1.w;
        }
        __syncthreads();
#pragma unroll
        for (int kk = 0; kk < 16; kk++) {
            float av[8];
            *reinterpret_cast<float4*>(&av[0]) = *reinterpret_cast<const float4*>(&As[kk][trow * 8]);
            *reinterpret_cast<float4*>(&av[4]) = *reinterpret_cast<const float4*>(&As[kk][trow * 8 + 4]);
            float bv[TN];
            *reinterpret_cast<float4*>(&bv[0]) = *reinterpret_cast<const float4*>(&Bs[kk][tcol * TN]);
            if constexpr (TN == 8)
                *reinterpret_cast<float4*>(&bv[4]) = *reinterpret_cast<const float4*>(&Bs[kk][tcol * TN + 4]);
#pragma unroll
            for (int i = 0; i < 8; i++)
#pragma unroll
                for (int j = 0; j < TN; j++) acc[i][j] = fmaf(av[i], bv[j], acc[i][j]);
        }
    }

    float* cout = sub ? g_base : g_y;
#pragma unroll
    for (int i = 0; i < 8; i++) {
        int rw = m0 + trow * 8 + i;
        float* cp = cout + (size_t)rw * ldc + o0 + tcol * TN;
        float4 v0 = make_float4(acc[i][0], acc[i][1], acc[i][2], acc[i][3]);
        *reinterpret_cast<float4*>(cp) = v0;
        if constexpr (TN == 8) {
            float4 v1 = make_float4(acc[i][4], acc[i][5], acc[i][6], acc[i][7]);
            *reinterpret_cast<float4*>(cp + 4) = v1;
        }
    }
}

// ---------------- stage5 column reduce: H (in g_pd) -> max/min/sums ---------
__global__ void k_red5() {
    int b = blockIdx.x >> 2;
    int o = ((blockIdx.x & 3) << 8) + threadIdx.x;   // 256 threads
    const float* p = g_pd + (size_t)b * 1024 * 1024 + o;
    float mx = -1e30f, mn = 1e30f, s = 0.f, s2 = 0.f;
#pragma unroll 8
    for (int n = 0; n < 1024; n++) {
        float v = p[(size_t)n * 1024];
        mx = fmaxf(mx, v); mn = fminf(mn, v);
        s += v; s2 += v * v;
    }
    g_max5[b * 1024 + o] = mx;
    g_min5[b * 1024 + o] = mn;
    g_sumslot[b * 1024 + o] = s;
    g_sqslot[b * 1024 + o]  = s2;
}

// ---------------- stage5 finalize: BN + LReLU on per-(b,o) extremum ---------
__global__ void k_final5(float* __restrict__ out) {
    int i = blockIdx.x * blockDim.x + threadIdx.x;   // 32768
    int o = i & 1023;
    float sc = g_scale[o];
    float v  = (sc >= 0.f) ? g_max5[i] : g_min5[i];
    float hv = fmaf(sc, v, g_bias[o]);
    out[i] = (hv >= 0.f) ? hv : 0.2f * hv;
}

// ---------------- orchestration ---------------------------------------------
extern "C" void kernel_launch(void* const* d_in, const int* in_sizes, int n_in,
                              void* d_out, int out_size) {
    const float* x = (const float*)d_in[0];
    const float *W1 = (const float*)d_in[1],  *G1 = (const float*)d_in[2],  *B1 = (const float*)d_in[3];
    const float *W2 = (const float*)d_in[4],  *G2 = (const float*)d_in[5],  *B2 = (const float*)d_in[6];
    const float *W3 = (const float*)d_in[7],  *G3 = (const float*)d_in[8],  *B3 = (const float*)d_in[9];
    const float *W4 = (const float*)d_in[10], *G4 = (const float*)d_in[11], *B4 = (const float*)d_in[12];
    const float *W5 = (const float*)d_in[13], *G5 = (const float*)d_in[14], *B5 = (const float*)d_in[15];
    float* out = (float*)d_out;

    cudaFuncSetAttribute(k_mma<true>,  cudaFuncAttributeMaxDynamicSharedMemorySize, SMEM_GRAM);
    cudaFuncSetAttribute(k_mma<false>, cudaFuncAttributeMaxDynamicSharedMemorySize, SMEM_FC);

    const float invE = 1.f / (float)((size_t)BN_ * KK);

    k_init<<<256, 256>>>();
    k_convW5<<<2048, 256>>>(W5);

    // ---- Stage 1: C=3, O=64, write cat[0:64) ----
    k_ybase1<<<BN_, 64>>>(x, W1);
    k_knn3b<<<BN_ / 32, 256>>>(x);
    k_edge_reduce<<<BN_, 64>>>(64);
    k_stats<<<4, 256>>>(G1, B1, 64, invE);
    k_apply<<<BN_ * 64 / 256, 256>>>(64, 0);

    // ---- Stage 2: in=cat[0:64), C=64, O=64 -> cat[64:128) ----
    k_gemm2m<64, 4><<<dim3(256, 1, 2), 256>>>(0, W2, 128, 64, 64);
    k_mma<true><<<dim3(256, 8), 256, SMEM_GRAM>>>(0, 4);
    k_diag<<<BN_ / 256, 256>>>();
    k_sel8<<<BN_ / 32, 256>>>();
    k_edge_reduce<<<BN_, 64>>>(64);
    k_stats<<<4, 256>>>(G2, B2, 64, invE);
    k_apply<<<BN_ * 64 / 256, 256>>>(64, 64);

    // ---- Stage 3: in=cat[64:128), C=64, O=128 -> cat[128:256) ----
    k_gemm2m<128, 8><<<dim3(256, 1, 2), 256>>>(64, W3, 128, 64, 128);
    k_mma<true><<<dim3(256, 8), 256, SMEM_GRAM>>>(64, 4);
    k_diag<<<BN_ / 256, 256>>>();
    k_sel8<<<BN_ / 32, 256>>>();
    k_edge_reduce<<<BN_, 128>>>(128);
    k_stats<<<4, 256>>>(G3, B3, 128, invE);
    k_apply<<<BN_ * 128 / 256, 256>>>(128, 128);

    // ---- Stage 4: in=cat[128:256), C=128, O=256 -> cat[256:512) ----
    k_gemm2m<128, 8><<<dim3(256, 2, 2), 256>>>(128, W4, 256, 128, 256);
    k_mma<true><<<dim3(256, 8), 256, SMEM_GRAM>>>(128, 8);
    k_diag<<<BN_ / 256, 256>>>();
    k_sel8<<<BN_ / 32, 256>>>();
    k_edge_reduce<<<BN_, 256>>>(256);
    k_stats<<<4, 256>>>(G4, B4, 256, invE);
    k_apply<<<BN_ * 256 / 256, 256>>>(256, 256);

    // ---- Stage 5: FC 512->1024 (mma, 2-way split) + BN + LReLU + max -------
    k_mma<false><<<dim3(256, 8), 256, SMEM_FC>>>(0, 32);
    k_red5<<<128, 256>>>();
    k_stats<<<4, 256>>>(G5, B5, 1024, 1.f / (float)BN_);
    k_final5<<<128, 256>>>(out);
}

// round 17
// speedup vs baseline: 2.4295x; 1.2422x over previous
#include <cuda_runtime.h>
#include <cuda_bf16.h>
#include <cstdint>

#define BB 32
#define NN 1024
#define KK 20
#define BN_ 32768          // BB*NN
#define NSLOT 64
#define SCAP 88            // superset buffer capacity per query

// ---------------- scratch (static __device__, no allocations) ----------------
__device__ float g_cat[BN_ * 512];            // x1|x2|x3|x4 concatenated per point
__device__ __nv_bfloat16 g_cath[BN_ * 512];   // bf16 3-way split of cat: hi
__device__ __nv_bfloat16 g_catm[BN_ * 512];   // mid
__device__ __nv_bfloat16 g_catl[BN_ * 512];   // lo
__device__ __nv_bfloat16 g_wh[1024 * 512];    // W5 hi
__device__ __nv_bfloat16 g_wl[1024 * 512];    // W5 lo
__device__ float g_y[BN_ * 256];         // y = x @ Wa^T
__device__ float g_base[BN_ * 256];      // base = x @ (Wb-Wa)^T
__device__ float g_hmax[BN_ * 256];
__device__ float g_hmin[BN_ * 256];
__device__ float g_pd[(size_t)BB * NN * NN];   // gram matrix / stage5 H (134MB)
__device__ float g_norm[BN_];
__device__ int   g_idx[BN_ * KK];
__device__ float g_sumslot[NSLOT * 1024];
__device__ float g_sqslot[NSLOT * 1024];
__device__ float g_scale[1024];
__device__ float g_bias[1024];
__device__ float g_max5[BB * 1024];
__device__ float g_min5[BB * 1024];

__device__ __forceinline__ unsigned encf(float f) {
    int i = __float_as_int(f);
    return (i >= 0) ? ((unsigned)i | 0x80000000u) : ~((unsigned)i);
}

// ---------------- init ------------------------------------------------------
__global__ void k_init() {
    int i = blockIdx.x * blockDim.x + threadIdx.x;
    if (i < NSLOT * 1024) { g_sumslot[i] = 0.f; g_sqslot[i] = 0.f; }
}

// ---------------- split W5 into bf16 hi/lo ----------------------------------
__global__ void k_convW5(const float* __restrict__ W5) {
    int i = blockIdx.x * blockDim.x + threadIdx.x;   // 1024*512
    float v = W5[i];
    __nv_bfloat16 h = __float2bfloat16(v);
    g_wh[i] = h;
    g_wl[i] = __float2bfloat16(v - __bfloat162float(h));
}

// ---------------- stage1 y/base (C=3, O=64) ---------------------------------
__global__ void k_ybase1(const float* __restrict__ x, const float* __restrict__ W) {
    int bn = blockIdx.x;
    int o  = threadIdx.x;   // 64
    __shared__ float xs[3];
    if (o < 3) xs[o] = x[bn * 3 + o];
    __syncthreads();
    const float* w = W + o * 6;
    float y  = w[0] * xs[0] + w[1] * xs[1] + w[2] * xs[2];
    float bs = (w[3] - w[0]) * xs[0] + (w[4] - w[1]) * xs[1] + (w[5] - w[2]) * xs[2];
    g_y[bn * 64 + o]    = y;
    g_base[bn * 64 + o] = bs;
}

// ======= selection core: threshold from local top-4 union + exact fixup =====
// 8 threads per query (sub = 0..7); thread handles candidates c=(8i+sub)*4+kk.
// KeyF4(i) -> float4 of those 4 keys. KeyF1(c) -> single key (fallback path).
template <typename F4, typename F1>
__device__ __forceinline__ void sel_core(
        F4 keyf4, F1 keyf1, int qi, int sub, int q,
        unsigned long long (*sb1)[32], unsigned long long (*sbuf)[SCAP],
        int* scnt, unsigned* sT0) {
    // ---- phase 1: local top-4 (packed: encf(key)<<32 | (1023-c)) ----
    unsigned long long loc[4] = {0ull, 0ull, 0ull, 0ull};
    for (int i = 0; i < 32; i++) {
        float4 k4 = keyf4(i);
        int c0 = (8 * i + sub) * 4;
        float ka[4] = {k4.x, k4.y, k4.z, k4.w};
#pragma unroll
        for (int kk = 0; kk < 4; kk++) {
            unsigned long long e =
                ((unsigned long long)encf(ka[kk]) << 32) | (unsigned)(1023 - (c0 + kk));
            if (e > loc[3]) {
#pragma unroll
                for (int r = 0; r < 4; r++) {
                    bool sw = e > loc[r];
                    unsigned long long t = loc[r];
                    loc[r] = sw ? e : t;
                    e = sw ? t : e;
                }
            }
        }
    }
#pragma unroll
    for (int r = 0; r < 4; r++) sb1[qi][sub * 4 + r] = loc[r];
    __syncthreads();
    // ---- phase 2: rank union of 32; unique rank-19 value -> T0 ----
#pragma unroll
    for (int r = 0; r < 4; r++) {
        unsigned long long my = sb1[qi][sub * 4 + r];
        int rk = 0;
#pragma unroll 8
        for (int t = 0; t < 32; t++) rk += (sb1[qi][t] > my);
        if (rk == 19) sT0[qi] = (unsigned)(my >> 32);
    }
    __syncthreads();
    unsigned T0r = sT0[qi];
    T0r = (T0r > 64u) ? T0r - 64u : 0u;   // relax 64 encoded ulps (superset guard)
    // ---- phase 3: collect superset via smem atomics ----
    for (int i = 0; i < 32; i++) {
        float4 k4 = keyf4(i);
        int c0 = (8 * i + sub) * 4;
        float ka[4] = {k4.x, k4.y, k4.z, k4.w};
#pragma unroll
        for (int kk = 0; kk < 4; kk++) {
            unsigned ek = encf(ka[kk]);
            if (ek >= T0r) {
                int pos = atomicAdd(&scnt[qi], 1);
                if (pos < SCAP)
                    sbuf[qi][pos] =
                        ((unsigned long long)ek << 32) | (unsigned)(1023 - (c0 + kk));
            }
        }
    }
    __syncthreads();
    int n = scnt[qi];
    if (n <= SCAP) {
        // ---- phase 4: exact rank among collected (desc value, asc index) ----
        for (int s = sub; s < n; s += 8) {
            unsigned long long my = sbuf[qi][s];
            int rk = 0;
            for (int t = 0; t < n; t++) rk += (sbuf[qi][t] > my);
            if (rk < KK) g_idx[(size_t)q * KK + rk] = 1023 - (int)(my & 0xFFFFFFFFull);
        }
    } else if (sub == 0) {
        // ---- fallback (near-never): serial 20-pass selection-sort ----
        unsigned long long prev = ~0ull;
        for (int r = 0; r < KK; r++) {
            unsigned long long best = 0ull;
            for (int c = 0; c < 1024; c++) {
                unsigned long long e =
                    ((unsigned long long)encf(keyf1(c)) << 32) | (unsigned)(1023 - c);
                if (e < prev && e > best) best = e;
            }
            g_idx[(size_t)q * KK + r] = 1023 - (int)(best & 0xFFFFFFFFull);
            prev = best;
        }
    }
}

// ---------------- stage-1 kNN selection (xyz in smem) -----------------------
__global__ __launch_bounds__(256) void k_selxyz2(const float* __restrict__ xin) {
    __shared__ float sx[1024], sy[1024], sz[1024], snn[1024];
    __shared__ unsigned long long sb1[32][32];
    __shared__ unsigned long long sbuf[32][SCAP];
    __shared__ int scnt[32];
    __shared__ unsigned sT0[32];
    int t = threadIdx.x, qi = t >> 3, sub = t & 7;
    int q = blockIdx.x * 32 + qi;
    int b = q >> 10;
    const float* xb = xin + (size_t)b * 1024 * 3;
    if (sub == 0) scnt[qi] = 0;
    for (int i = t; i < 1024; i += 256) {
        float vx = xb[i * 3], vy = xb[i * 3 + 1], vz = xb[i * 3 + 2];
        sx[i] = vx; sy[i] = vy; sz[i] = vz;
        snn[i] = vx * vx + vy * vy + vz * vz;
    }
    __syncthreads();
    int n0 = q & 1023;
    float qx = sx[n0], qy = sy[n0], qz = sz[n0], qq = snn[n0];
    auto keyf1 = [&](int c) {
        return 2.f * (qx * sx[c] + qy * sy[c] + qz * sz[c]) - qq - snn[c];
    };
    auto keyf4 = [&](int i) {
        int c = (8 * i + sub) * 4;
        return make_float4(keyf1(c), keyf1(c + 1), keyf1(c + 2), keyf1(c + 3));
    };
    sel_core(keyf4, keyf1, qi, sub, q, sb1, sbuf, scnt, sT0);
}

// ---------------- gram selection (rows of g_pd) -----------------------------
__global__ __launch_bounds__(256) void k_selpd2() {
    __shared__ float snn[1024];
    __shared__ unsigned long long sb1[32][32];
    __shared__ unsigned long long sbuf[32][SCAP];
    __shared__ int scnt[32];
    __shared__ unsigned sT0[32];
    int t = threadIdx.x, qi = t >> 3, sub = t & 7;
    int q = blockIdx.x * 32 + qi;
    int b = q >> 10;
    if (sub == 0) scnt[qi] = 0;
    for (int i = t; i < 1024; i += 256) snn[i] = g_norm[(b << 10) + i];
    __syncthreads();
    float qq = snn[q & 1023];
    const float4* row4 = (const float4*)(g_pd + (size_t)q * NN);
    auto keyf1 = [&](int c) {
        return 2.f * __ldg(g_pd + (size_t)q * NN + c) - qq - snn[c];
    };
    auto keyf4 = [&](int i) {
        int j = 8 * i + sub;
        float4 p = __ldg(row4 + j);
        float4 nn = *reinterpret_cast<const float4*>(&snn[4 * j]);
        return make_float4(2.f * p.x - qq - nn.x, 2.f * p.y - qq - nn.y,
                           2.f * p.z - qq - nn.z, 2.f * p.w - qq - nn.w);
    };
    sel_core(keyf4, keyf1, qi, sub, q, sb1, sbuf, scnt, sT0);
}

// ---------------- diag of gram -> candidate norms ---------------------------
__global__ void k_diag() {
    int q = blockIdx.x * blockDim.x + threadIdx.x;
    if (q < BN_) g_norm[q] = g_pd[(size_t)q * NN + (q & 1023)];
}

// ---------------- gather-reduce over k neighbors ----------------------------
__global__ void k_edge_reduce(int O) {
    int bn = blockIdx.x;
    int o  = threadIdx.x;       // O threads
    int b  = bn >> 10;
    __shared__ int soff[KK];
    if (o < KK) soff[o] = ((b << 10) + g_idx[(size_t)bn * KK + o]) * O;
    __syncthreads();
    float bs = g_base[(size_t)bn * O + o];
    float mx = -1e30f, mn = 1e30f, s = 0.f, s2 = 0.f;
#pragma unroll
    for (int j = 0; j < KK; j++) {
        float v = g_y[soff[j] + o] + bs;
        mx = fmaxf(mx, v); mn = fminf(mn, v);
        s += v; s2 += v * v;
    }
    g_hmax[(size_t)bn * O + o] = mx;
    g_hmin[(size_t)bn * O + o] = mn;
    int slot = bn & (NSLOT - 1);
    atomicAdd(&g_sumslot[slot * 1024 + o], s);
    atomicAdd(&g_sqslot[slot * 1024 + o], s2);
}

// ---------------- BN stats finalize (and rezero slots) ----------------------
__global__ void k_stats(const float* __restrict__ g, const float* __restrict__ bt,
                        int O, float invcnt) {
    int o = blockIdx.x * blockDim.x + threadIdx.x;   // 1024 threads total
    float s = 0.f, s2 = 0.f;
    for (int sl = 0; sl < NSLOT; sl++) {
        s  += g_sumslot[sl * 1024 + o];
        s2 += g_sqslot[sl * 1024 + o];
        g_sumslot[sl * 1024 + o] = 0.f;
        g_sqslot[sl * 1024 + o]  = 0.f;
    }
    if (o < O) {
        float mean = s * invcnt;
        float var  = fmaxf(s2 * invcnt - mean * mean, 0.f);
        float sc   = g[o] * rsqrtf(var + 1e-5f);
        g_scale[o] = sc;
        g_bias[o]  = bt[o] - mean * sc;
    }
}

// -------- apply BN + LReLU to max/min, write cat + 3-way bf16 split ---------
__global__ void k_apply(int O, int coff) {
    int i = blockIdx.x * blockDim.x + threadIdx.x;
    if (i >= BN_ * O) return;
    int o  = i & (O - 1);        // O is a power of two
    int bn = i / O;
    float sc = g_scale[o];
    float v  = (sc >= 0.f) ? g_hmax[i] : g_hmin[i];
    float hv = fmaf(sc, v, g_bias[o]);
    float r  = (hv >= 0.f) ? hv : 0.2f * hv;
    size_t ci = (size_t)bn * 512 + coff + o;
    g_cat[ci] = r;
    __nv_bfloat16 h = __float2bfloat16(r);
    float rm = r - __bfloat162float(h);
    __nv_bfloat16 m = __float2bfloat16(rm);
    g_cath[ci] = h;
    g_catm[ci] = m;
    g_catl[ci] = __float2bfloat16(rm - __bfloat162float(m));
}

// ================= bf16-split tensor-core GEMM (mma.sync, sm_80 path) =======
#define LDX4(f, addr) \
    asm volatile("ldmatrix.sync.aligned.m8n8.x4.shared.b16 {%0,%1,%2,%3}, [%4];" \
        : "=r"((f)[0]), "=r"((f)[1]), "=r"((f)[2]), "=r"((f)[3]) : "r"(addr))
#define MMA16816(d, a, b0, b1) \
    asm volatile("mma.sync.aligned.m16n8k16.row.col.f32.bf16.bf16.f32 " \
        "{%0,%1,%2,%3},{%4,%5,%6,%7},{%8,%9},{%0,%1,%2,%3};" \
        : "+f"((d)[0]), "+f"((d)[1]), "+f"((d)[2]), "+f"((d)[3]) \
        : "r"((a)[0]), "r"((a)[1]), "r"((a)[2]), "r"((a)[3]), "r"(b0), "r"(b1))

static constexpr int MT_BYTES = 128 * 48;        // one 128x16 bf16 tile, 48B rows

template <bool GRAM>
__global__ __launch_bounds__(256) void k_mma(int aoff, int nchunk) {
    constexpr int NMA  = GRAM ? 3 : 2;
    constexpr int NMB  = GRAM ? 3 : 2;
    constexpr int NMAT = NMA + NMB;
    constexpr int BUFB = NMAT * MT_BYTES;

    extern __shared__ char smem[];
    uint32_t sb;
    asm("{ .reg .u64 t; cvta.to.shared.u64 t, %1; cvt.u32.u64 %0, t; }" : "=r"(sb) : "l"(smem));

    const int tid  = threadIdx.x;
    const int lane = tid & 31;
    const int wid  = tid >> 5;
    const int wm   = wid & 3;          // 4 warps along M
    const int wn   = wid >> 2;         // 2 warps along N
    const int m0   = blockIdx.x * 128;
    const int o0   = blockIdx.y * 128;

    const int row  = tid >> 1;
    const int half = tid & 1;
    const __nv_bfloat16* gbase[NMAT];
    {
        size_t aio = (size_t)(m0 + row) * 512 + aoff + half * 8;
        gbase[0] = g_cath + aio;
        gbase[1] = g_catm + aio;
        if constexpr (GRAM) gbase[2] = g_catl + aio;
    }
    if constexpr (GRAM) {
        size_t bio = (size_t)((m0 & ~1023) + o0 + row) * 512 + aoff + half * 8;
        gbase[NMA + 0] = g_cath + bio;
        gbase[NMA + 1] = g_catm + bio;
        gbase[NMA + 2] = g_catl + bio;
    } else {
        size_t bio = (size_t)(o0 + row) * 512 + half * 8;
        gbase[NMA + 0] = g_wh + bio;
        gbase[NMA + 1] = g_wl + bio;
    }
    uint32_t soff[NMAT];
#pragma unroll
    for (int j = 0; j < NMAT; j++) soff[j] = sb + j * MT_BYTES + row * 48 + half * 16;

    auto issue = [&](int c, int buf) {
#pragma unroll
        for (int j = 0; j < NMAT; j++) {
            uint32_t sa = soff[j] + buf * BUFB;
            const __nv_bfloat16* gp = gbase[j] + c * 16;
            asm volatile("cp.async.cg.shared.global [%0], [%1], 16;" :: "r"(sa), "l"(gp));
        }
        asm volatile("cp.async.commit_group;");
    };

    const int arow = (lane & 7) + ((lane >> 3) & 1) * 8;   // A tiles: m-rows
    const int acb  = (lane >> 4) * 16;                     // +16B for k8-15
    const int brow = (lane & 7) + ((lane >> 4) & 1) * 8;   // B tiles: n-rows
    const int bcb  = ((lane >> 3) & 1) * 16;

    float acc[2][8][4];
#pragma unroll
    for (int i = 0; i < 2; i++)
#pragma unroll
        for (int j = 0; j < 8; j++)
#pragma unroll
            for (int q = 0; q < 4; q++) acc[i][j][q] = 0.f;

    issue(0, 0);

    for (int c = 0; c < nchunk; c++) {
        if (c + 1 < nchunk) {
            issue(c + 1, (c + 1) & 1);
            asm volatile("cp.async.wait_group 1;");
        } else {
            asm volatile("cp.async.wait_group 0;");
        }
        __syncthreads();

        const uint32_t bufb = sb + (c & 1) * BUFB;

        uint32_t am[NMA][2][4];
#pragma unroll
        for (int i = 0; i < 2; i++) {
            uint32_t aoffb = (wm * 32 + i * 16 + arow) * 48 + acb;
#pragma unroll
            for (int ma = 0; ma < NMA; ma++)
                LDX4(am[ma][i], bufb + ma * MT_BYTES + aoffb);
        }
#pragma unroll
        for (int g = 0; g < 4; g++) {
            uint32_t boffb = (wn * 64 + g * 16 + brow) * 48 + bcb;
            uint32_t bm[NMB][4];
#pragma unroll
            for (int mb = 0; mb < NMB; mb++)
                LDX4(bm[mb], bufb + (NMA + mb) * MT_BYTES + boffb);
#pragma unroll
            for (int i = 0; i < 2; i++) {
                if constexpr (GRAM) {
                    MMA16816(acc[i][2 * g],     am[0][i], bm[0][0], bm[0][1]);
                    MMA16816(acc[i][2 * g],     am[0][i], bm[1][0], bm[1][1]);
                    MMA16816(acc[i][2 * g],     am[1][i], bm[0][0], bm[0][1]);
                    MMA16816(acc[i][2 * g],     am[0][i], bm[2][0], bm[2][1]);
                    MMA16816(acc[i][2 * g],     am[1][i], bm[1][0], bm[1][1]);
                    MMA16816(acc[i][2 * g],     am[2][i], bm[0][0], bm[0][1]);
                    MMA16816(acc[i][2 * g + 1], am[0][i], bm[0][2], bm[0][3]);
                    MMA16816(acc[i][2 * g + 1], am[0][i], bm[1][2], bm[1][3]);
                    MMA16816(acc[i][2 * g + 1], am[1][i], bm[0][2], bm[0][3]);
                    MMA16816(acc[i][2 * g + 1], am[0][i], bm[2][2], bm[2][3]);
                    MMA16816(acc[i][2 * g + 1], am[1][i], bm[1][2], bm[1][3]);
                    MMA16816(acc[i][2 * g + 1], am[2][i], bm[0][2], bm[0][3]);
                } else {
                    MMA16816(acc[i][2 * g],     am[0][i], bm[0][0], bm[0][1]);
                    MMA16816(acc[i][2 * g],     am[0][i], bm[1][0], bm[1][1]);
                    MMA16816(acc[i][2 * g],     am[1][i], bm[0][0], bm[0][1]);
                    MMA16816(acc[i][2 * g + 1], am[0][i], bm[0][2], bm[0][3]);
                    MMA16816(acc[i][2 * g + 1], am[0][i], bm[1][2], bm[1][3]);
                    MMA16816(acc[i][2 * g + 1], am[1][i], bm[0][2], bm[0][3]);
                }
            }
        }
        __syncthreads();
    }

#pragma unroll
    for (int i = 0; i < 2; i++) {
        int r0 = m0 + wm * 32 + i * 16 + (lane >> 2);
#pragma unroll
        for (int jb = 0; jb < 8; jb++) {
            int col = o0 + wn * 64 + jb * 8 + (lane & 3) * 2;
            *reinterpret_cast<float2*>(&g_pd[(size_t)r0 * 1024 + col]) =
                make_float2(acc[i][jb][0], acc[i][jb][1]);
            *reinterpret_cast<float2*>(&g_pd[(size_t)(r0 + 8) * 1024 + col]) =
                make_float2(acc[i][jb][2], acc[i][jb][3]);
        }
    }
}

static constexpr int SMEM_GRAM = 2 * 6 * MT_BYTES;   // 73728
static constexpr int SMEM_FC   = 2 * 4 * MT_BYTES;   // 49152

// ------- merged fp32 SGEMM for y AND base: blockIdx.z selects output --------
template <int BNT, int TN>
__global__ __launch_bounds__(256) void k_gemm2m(
        int aoff, const float* __restrict__ W, int ldw, int Ktot, int ldc) {
    __shared__ float As[16][128];
    __shared__ float Bs[16][BNT];
    const float* A = g_cat + aoff;
    const int lda = 512;
    const int m0 = blockIdx.x * 128;
    const int o0 = blockIdx.y * BNT;
    const bool sub = (blockIdx.z != 0);
    const int coff = sub ? (ldw >> 1) : 0;
    const int tid = threadIdx.x;
    const int trow = tid >> 4;
    const int tcol = tid & 15;

    float acc[8][TN];
#pragma unroll
    for (int i = 0; i < 8; i++)
#pragma unroll
        for (int j = 0; j < TN; j++) acc[i][j] = 0.f;

    const int arow = tid >> 1, akoff = (tid & 1) * 8;
    int brow, bkoff;
    if (BNT == 128) { brow = tid >> 1; bkoff = (tid & 1) * 8; }
    else            { brow = tid >> 2; bkoff = (tid & 3) * 4; }

    const float* bbaseptr = W + (size_t)o0 * ldw;

    for (int kt = 0; kt < Ktot; kt += 16) {
        const float* ap = A + (size_t)(m0 + arow) * lda + kt + akoff;
        float4 a0 = *reinterpret_cast<const float4*>(ap);
        float4 a1 = *reinterpret_cast<const float4*>(ap + 4);
        const float* bp = bbaseptr + (size_t)brow * ldw + coff + kt + bkoff;
        float4 b0 = *reinterpret_cast<const float4*>(bp);
        float4 b1;
        if constexpr (BNT == 128) b1 = *reinterpret_cast<const float4*>(bp + 4);
        if (sub) {
            const float* sp = bbaseptr + (size_t)brow * ldw + kt + bkoff;
            float4 s0 = *reinterpret_cast<const float4*>(sp);
            b0.x -= s0.x; b0.y -= s0.y; b0.z -= s0.z; b0.w -= s0.w;
            if constexpr (BNT == 128) {
                float4 s1 = *reinterpret_cast<const float4*>(sp + 4);
                b1.x -= s1.x; b1.y -= s1.y; b1.z -= s1.z; b1.w -= s1.w;
            }
        }
        __syncthreads();
        As[akoff + 0][arow] = a0.x; As[akoff + 1][arow] = a0.y;
        As[akoff + 2][arow] = a0.z; As[akoff + 3][arow] = a0.w;
        As[akoff + 4][arow] = a1.x; As[akoff + 5][arow] = a1.y;
        As[akoff + 6][arow] = a1.z; As[akoff + 7][arow] = a1.w;
        Bs[bkoff + 0][brow] = b0.x; Bs[bkoff + 1][brow] = b0.y;
        Bs[bkoff + 2][brow] = b0.z; Bs[bkoff + 3][brow] = b0.w;
        if constexpr (BNT == 128) {
            Bs[bkoff + 4][brow] = b1.x; Bs[bkoff + 5][brow] = b1.y;
            Bs[bkoff + 6][brow] = b1.z; Bs[bkoff + 7][brow] = b1.w;
        }
        __syncthreads();
#pragma unroll
        for (int kk = 0; kk < 16; kk++) {
            float av[8];
            *reinterpret_cast<float4*>(&av[0]) = *reinterpret_cast<const float4*>(&As[kk][trow * 8]);
            *reinterpret_cast<float4*>(&av[4]) = *reinterpret_cast<const float4*>(&As[kk][trow * 8 + 4]);
            float bv[TN];
            *reinterpret_cast<float4*>(&bv[0]) = *reinterpret_cast<const float4*>(&Bs[kk][tcol * TN]);
            if constexpr (TN == 8)
                *reinterpret_cast<float4*>(&bv[4]) = *reinterpret_cast<const float4*>(&Bs[kk][tcol * TN + 4]);
#pragma unroll
            for (int i = 0; i < 8; i++)
#pragma unroll
                for (int j = 0; j < TN; j++) acc[i][j] = fmaf(av[i], bv[j], acc[i][j]);
        }
    }

    float* cout = sub ? g_base : g_y;
#pragma unroll
    for (int i = 0; i < 8; i++) {
        int rw = m0 + trow * 8 + i;
        float* cp = cout + (size_t)rw * ldc + o0 + tcol * TN;
        float4 v0 = make_float4(acc[i][0], acc[i][1], acc[i][2], acc[i][3]);
        *reinterpret_cast<float4*>(cp) = v0;
        if constexpr (TN == 8) {
            float4 v1 = make_float4(acc[i][4], acc[i][5], acc[i][6], acc[i][7]);
            *reinterpret_cast<float4*>(cp + 4) = v1;
        }
    }
}

// ---------------- stage5 column reduce: H (in g_pd) -> max/min/sums ---------
__global__ void k_red5() {
    int b = blockIdx.x >> 2;
    int o = ((blockIdx.x & 3) << 8) + threadIdx.x;   // 256 threads
    const float* p = g_pd + (size_t)b * 1024 * 1024 + o;
    float mx = -1e30f, mn = 1e30f, s = 0.f, s2 = 0.f;
#pragma unroll 8
    for (int n = 0; n < 1024; n++) {
        float v = p[(size_t)n * 1024];
        mx = fmaxf(mx, v); mn = fminf(mn, v);
        s += v; s2 += v * v;
    }
    g_max5[b * 1024 + o] = mx;
    g_min5[b * 1024 + o] = mn;
    g_sumslot[b * 1024 + o] = s;
    g_sqslot[b * 1024 + o]  = s2;
}

// ---------------- stage5 finalize: BN + LReLU on per-(b,o) extremum ---------
__global__ void k_final5(float* __restrict__ out) {
    int i = blockIdx.x * blockDim.x + threadIdx.x;   // 32768
    int o = i & 1023;
    float sc = g_scale[o];
    float v  = (sc >= 0.f) ? g_max5[i] : g_min5[i];
    float hv = fmaf(sc, v, g_bias[o]);
    out[i] = (hv >= 0.f) ? hv : 0.2f * hv;
}

// ---------------- orchestration ---------------------------------------------
extern "C" void kernel_launch(void* const* d_in, const int* in_sizes, int n_in,
                              void* d_out, int out_size) {
    const float* x = (const float*)d_in[0];
    const float *W1 = (const float*)d_in[1],  *G1 = (const float*)d_in[2],  *B1 = (const float*)d_in[3];
    const float *W2 = (const float*)d_in[4],  *G2 = (const float*)d_in[5],  *B2 = (const float*)d_in[6];
    const float *W3 = (const float*)d_in[7],  *G3 = (const float*)d_in[8],  *B3 = (const float*)d_in[9];
    const float *W4 = (const float*)d_in[10], *G4 = (const float*)d_in[11], *B4 = (const float*)d_in[12];
    const float *W5 = (const float*)d_in[13], *G5 = (const float*)d_in[14], *B5 = (const float*)d_in[15];
    float* out = (float*)d_out;

    cudaFuncSetAttribute(k_mma<true>,  cudaFuncAttributeMaxDynamicSharedMemorySize, SMEM_GRAM);
    cudaFuncSetAttribute(k_mma<false>, cudaFuncAttributeMaxDynamicSharedMemorySize, SMEM_FC);

    const float invE = 1.f / (float)((size_t)BN_ * KK);

    k_init<<<256, 256>>>();
    k_convW5<<<2048, 256>>>(W5);

    // ---- Stage 1: C=3, O=64, write cat[0:64) ----
    k_ybase1<<<BN_, 64>>>(x, W1);
    k_selxyz2<<<BN_ / 32, 256>>>(x);
    k_edge_reduce<<<BN_, 64>>>(64);
    k_stats<<<4, 256>>>(G1, B1, 64, invE);
    k_apply<<<BN_ * 64 / 256, 256>>>(64, 0);

    // ---- Stage 2: in=cat[0:64), C=64, O=64 -> cat[64:128) ----
    k_gemm2m<64, 4><<<dim3(256, 1, 2), 256>>>(0, W2, 128, 64, 64);
    k_mma<true><<<dim3(256, 8), 256, SMEM_GRAM>>>(0, 4);
    k_diag<<<BN_ / 256, 256>>>();
    k_selpd2<<<BN_ / 32, 256>>>();
    k_edge_reduce<<<BN_, 64>>>(64);
    k_stats<<<4, 256>>>(G2, B2, 64, invE);
    k_apply<<<BN_ * 64 / 256, 256>>>(64, 64);

    // ---- Stage 3: in=cat[64:128), C=64, O=128 -> cat[128:256) ----
    k_gemm2m<128, 8><<<dim3(256, 1, 2), 256>>>(64, W3, 128, 64, 128);
    k_mma<true><<<dim3(256, 8), 256, SMEM_GRAM>>>(64, 4);
    k_diag<<<BN_ / 256, 256>>>();
    k_selpd2<<<BN_ / 32, 256>>>();
    k_edge_reduce<<<BN_, 128>>>(128);
    k_stats<<<4, 256>>>(G3, B3, 128, invE);
    k_apply<<<BN_ * 128 / 256, 256>>>(128, 128);

    // ---- Stage 4: in=cat[128:256), C=128, O=256 -> cat[256:512) ----
    k_gemm2m<128, 8><<<dim3(256, 2, 2), 256>>>(128, W4, 256, 128, 256);
    k_mma<true><<<dim3(256, 8), 256, SMEM_GRAM>>>(128, 8);
    k_diag<<<BN_ / 256, 256>>>();
    k_selpd2<<<BN_ / 32, 256>>>();
    k_edge_reduce<<<BN_, 256>>>(256);
    k_stats<<<4, 256>>>(G4, B4, 256, invE);
    k_apply<<<BN_ * 256 / 256, 256>>>(256, 256);

    // ---- Stage 5: FC 512->1024 (mma, 2-way split) + BN + LReLU + max -------
    k_mma<false><<<dim3(256, 8), 256, SMEM_FC>>>(0, 32);
    k_red5<<<128, 256>>>();
    k_stats<<<4, 256>>>(G5, B5, 1024, 1.f / (float)BN_);
    k_final5<<<128, 256>>>(out);
}